// round 3
// baseline (speedup 1.0000x reference)
#include <cuda_runtime.h>

#define B_ 8
#define T_ 2048
#define H_ 1024
#define P_ 64
#define BT_ (B_ * T_)

// Scratch (no cudaMalloc allowed): Q, K, V, attention output, each [BT, P] fp32 = 4 MB
__device__ float g_q[BT_ * P_];
__device__ float g_k[BT_ * P_];
__device__ float g_v[BT_ * P_];
__device__ float g_att[BT_ * P_];

// ---------------------------------------------------------------------------
// Kernel 1: fused QKV projection.  out = X[16384,1024] @ W[1024,64] + b
// grid (M/128, 3), block 256.  BM=128, BN=64, BK=16, thread tile 8x4.
// ---------------------------------------------------------------------------
__global__ __launch_bounds__(256) void qkv_gemm(
    const float* __restrict__ X,
    const float* __restrict__ Wq, const float* __restrict__ bq,
    const float* __restrict__ Wk, const float* __restrict__ bk,
    const float* __restrict__ Wv, const float* __restrict__ bv)
{
    const int mat = blockIdx.y;
    const float* W  = (mat == 0) ? Wq : ((mat == 1) ? Wk : Wv);
    const float* bb = (mat == 0) ? bq : ((mat == 1) ? bk : bv);
    float* out      = (mat == 0) ? g_q : ((mat == 1) ? g_k : g_v);

    __shared__ float As[16][132];   // As[k][m], stride 132 (16B aligned, low conflict)
    __shared__ float Bs[16][64];    // Bs[k][n]

    const int tid = threadIdx.x;
    const int m0  = blockIdx.x * 128;
    const int ty  = tid >> 4;          // 0..15 -> rows ty*8..ty*8+7
    const int tx  = tid & 15;          // 0..15 -> cols tx*4..tx*4+3
    const int lr  = tid >> 2;          // X load row (0..63, +64 on pass 2)
    const int lc  = (tid & 3) << 2;    // X load col quad
    const int wr  = tid >> 4;          // W load row (0..15)
    const int wc  = (tid & 15) << 2;   // W load col quad

    float acc[8][4];
#pragma unroll
    for (int j = 0; j < 8; j++)
#pragma unroll
        for (int c = 0; c < 4; c++) acc[j][c] = 0.f;

    for (int k0 = 0; k0 < H_; k0 += 16) {
#pragma unroll
        for (int p = 0; p < 2; p++) {
            float4 xv = *(const float4*)(X + (size_t)(m0 + lr + 64 * p) * H_ + k0 + lc);
            As[lc + 0][lr + 64 * p] = xv.x;
            As[lc + 1][lr + 64 * p] = xv.y;
            As[lc + 2][lr + 64 * p] = xv.z;
            As[lc + 3][lr + 64 * p] = xv.w;
        }
        *(float4*)&Bs[wr][wc] = *(const float4*)(W + (size_t)(k0 + wr) * P_ + wc);
        __syncthreads();
#pragma unroll
        for (int kk = 0; kk < 16; kk++) {
            float4 a0 = *(const float4*)&As[kk][ty * 8];
            float4 a1 = *(const float4*)&As[kk][ty * 8 + 4];
            float4 b0 = *(const float4*)&Bs[kk][tx * 4];
            float a[8] = {a0.x, a0.y, a0.z, a0.w, a1.x, a1.y, a1.z, a1.w};
            float b[4] = {b0.x, b0.y, b0.z, b0.w};
#pragma unroll
            for (int j = 0; j < 8; j++)
#pragma unroll
                for (int c = 0; c < 4; c++) acc[j][c] += a[j] * b[c];
        }
        __syncthreads();
    }

    float bvv[4];
#pragma unroll
    for (int c = 0; c < 4; c++) bvv[c] = bb[tx * 4 + c];
#pragma unroll
    for (int j = 0; j < 8; j++) {
        float4 o;
        o.x = acc[j][0] + bvv[0];
        o.y = acc[j][1] + bvv[1];
        o.z = acc[j][2] + bvv[2];
        o.w = acc[j][3] + bvv[3];
        *(float4*)(out + (size_t)(m0 + ty * 8 + j) * P_ + tx * 4) = o;
    }
}

// ---------------------------------------------------------------------------
// Kernel 2: banded attention.
// The |i-j|>64 entries get -10000 added -> exp underflows to exactly 0 in fp32,
// so attention is exactly a band of 129 columns.  The padding-mask term is a
// per-row constant -> softmax-invariant -> dropped (exact).
// Bias gather only needs bias[1984 .. 2112] (129 values).
// One block = one (batch, 64-query-row tile).  Band of 192 K/V rows in smem.
// ---------------------------------------------------------------------------
#define KSTR 66   // row stride in floats: even (float2-aligned), conflict-free mod 32
#define ATTN_SMEM_FLOATS (192 * KSTR * 2 + 64 * KSTR + 132 + 8 * 132)
#define ATTN_SMEM_BYTES  (ATTN_SMEM_FLOATS * 4)

__global__ __launch_bounds__(256) void attn_kernel(const float* __restrict__ biasg)
{
    extern __shared__ float sm[];
    float* Ks     = sm;                     // [192][KSTR]
    float* Vs     = sm + 192 * KSTR;        // [192][KSTR]
    float* Qs     = sm + 2 * 192 * KSTR;    // [64][KSTR]
    float* bias_s = Qs + 64 * KSTR;         // [132]
    float* probs  = bias_s + 132;           // [8][132]

    const int tid = threadIdx.x;
    const int b   = blockIdx.x >> 5;         // 32 tiles per batch (2048/64)
    const int t0  = (blockIdx.x & 31) << 6;  // query tile start

    const float* Kg = g_k + (size_t)b * T_ * P_;
    const float* Vg = g_v + (size_t)b * T_ * P_;
    const float* Qg = g_q + ((size_t)b * T_ + t0) * P_;

    // Stage K/V band rows [t0-64, t0+127] (zero-fill out of range)
    for (int idx = tid; idx < 192 * 16; idx += 256) {
        int jj = idx >> 4;
        int c4 = (idx & 15) << 2;
        int j  = t0 - 64 + jj;
        float4 kv = make_float4(0.f, 0.f, 0.f, 0.f);
        float4 vv = make_float4(0.f, 0.f, 0.f, 0.f);
        if (j >= 0 && j < T_) {
            kv = *(const float4*)(Kg + (size_t)j * P_ + c4);
            vv = *(const float4*)(Vg + (size_t)j * P_ + c4);
        }
        float* kd = Ks + jj * KSTR + c4;
        kd[0] = kv.x; kd[1] = kv.y; kd[2] = kv.z; kd[3] = kv.w;
        float* vd = Vs + jj * KSTR + c4;
        vd[0] = vv.x; vd[1] = vv.y; vd[2] = vv.z; vd[3] = vv.w;
    }
    // Stage Q tile
    for (int idx = tid; idx < 64 * 16; idx += 256) {
        int r  = idx >> 4;
        int c4 = (idx & 15) << 2;
        float4 qv = *(const float4*)(Qg + (size_t)r * P_ + c4);
        float* qd = Qs + r * KSTR + c4;
        qd[0] = qv.x; qd[1] = qv.y; qd[2] = qv.z; qd[3] = qv.w;
    }
    // Stage bias window: bias[2048 - (t-j)] with d = (j - t + 64) in [0,128]
    for (int d = tid; d < 132; d += 256)
        bias_s[d] = (d <= 128) ? biasg[1984 + d] : 0.f;
    __syncthreads();

    const int w    = tid >> 5;
    const int lane = tid & 31;
    float* pw = probs + w * 132;

    for (int rr = 0; rr < 8; rr++) {
        const int r = w * 8 + rr;
        const int t = t0 + r;
        const float2* qr = (const float2*)(Qs + r * KSTR);

        // scores: lane handles band offsets d = c*32 + lane (d in [0,128])
        float sc[5];
#pragma unroll
        for (int c = 0; c < 5; c++) {
            int d  = c * 32 + lane;
            int jj = r + d;                // local K row (always < 192)
            int j  = t0 - 64 + jj;         // global key index
            float s = -1e30f;
            if (d <= 128 && j >= 0 && j < T_) {
                const float2* kr = (const float2*)(Ks + jj * KSTR);
                float dot = 0.f;
#pragma unroll
                for (int p = 0; p < 32; p++) {
                    float2 qa = qr[p], ka = kr[p];
                    dot += qa.x * ka.x + qa.y * ka.y;
                }
                s = dot * 0.125f + bias_s[d];   // 1/sqrt(P)=0.125 exact
            }
            sc[c] = s;
        }
        // softmax over the band
        float mx = sc[0];
#pragma unroll
        for (int c = 1; c < 5; c++) mx = fmaxf(mx, sc[c]);
#pragma unroll
        for (int off = 16; off > 0; off >>= 1)
            mx = fmaxf(mx, __shfl_xor_sync(0xffffffffu, mx, off));
        float ssum = 0.f;
#pragma unroll
        for (int c = 0; c < 5; c++) {
            float e = (sc[c] > -1e29f) ? __expf(sc[c] - mx) : 0.f;
            sc[c] = e;
            ssum += e;
        }
#pragma unroll
        for (int off = 16; off > 0; off >>= 1)
            ssum += __shfl_xor_sync(0xffffffffu, ssum, off);
        float inv = 1.f / ssum;
#pragma unroll
        for (int c = 0; c < 5; c++) {
            int d = c * 32 + lane;
            if (d <= 128) pw[d] = sc[c] * inv;
        }
        __syncwarp();

        // AV: lane accumulates output dims (2*lane, 2*lane+1) over the band
        float ox = 0.f, oy = 0.f;
#pragma unroll 4
        for (int d = 0; d < 129; d++) {
            float pb = pw[d];
            const float2* vr = (const float2*)(Vs + (r + d) * KSTR);
            float2 vv = vr[lane];
            ox += pb * vv.x;
            oy += pb * vv.y;
        }
        float2* ob = (float2*)(g_att + ((size_t)b * T_ + t) * P_);
        ob[lane] = make_float2(ox, oy);
        __syncwarp();   // pw is reused next row
    }
}

// ---------------------------------------------------------------------------
// Kernel 3: output projection.  O[16384,1024] = A[16384,64] @ Wo[64,1024] + bo
// grid (256, 8), block 256.  BM=64, BN=128, full K=64 in smem, thread tile 4x8.
// ---------------------------------------------------------------------------
__global__ __launch_bounds__(256) void outproj_kernel(
    const float* __restrict__ Wo, const float* __restrict__ bo,
    float* __restrict__ O)
{
    __shared__ float As[64][68];    // As[k][m], stride 68 (16B aligned)
    __shared__ float Ws[64][128];   // Ws[k][n]

    const int tid = threadIdx.x;
    const int m0  = blockIdx.x << 6;
    const int n0  = blockIdx.y << 7;

    for (int idx = tid; idx < 64 * 16; idx += 256) {
        int r  = idx >> 4;
        int c4 = (idx & 15) << 2;
        float4 av = *(const float4*)(g_att + (size_t)(m0 + r) * P_ + c4);
        As[c4 + 0][r] = av.x;
        As[c4 + 1][r] = av.y;
        As[c4 + 2][r] = av.z;
        As[c4 + 3][r] = av.w;
    }
    for (int idx = tid; idx < 64 * 32; idx += 256) {
        int r  = idx >> 5;
        int c4 = (idx & 31) << 2;
        *(float4*)&Ws[r][c4] = *(const float4*)(Wo + (size_t)r * H_ + n0 + c4);
    }
    __syncthreads();

    const int ty = tid >> 4;   // rows ty*4..ty*4+3
    const int tx = tid & 15;   // cols tx*8..tx*8+7
    float acc[4][8];
#pragma unroll
    for (int j = 0; j < 4; j++)
#pragma unroll
        for (int c = 0; c < 8; c++) acc[j][c] = 0.f;

#pragma unroll 8
    for (int k = 0; k < 64; k++) {
        float4 a0 = *(const float4*)&As[k][ty * 4];
        float4 b0 = *(const float4*)&Ws[k][tx * 8];
        float4 b1 = *(const float4*)&Ws[k][tx * 8 + 4];
        float a[4] = {a0.x, a0.y, a0.z, a0.w};
        float b[8] = {b0.x, b0.y, b0.z, b0.w, b1.x, b1.y, b1.z, b1.w};
#pragma unroll
        for (int j = 0; j < 4; j++)
#pragma unroll
            for (int c = 0; c < 8; c++) acc[j][c] += a[j] * b[c];
    }

    float bv[8];
#pragma unroll
    for (int c = 0; c < 8; c++) bv[c] = bo[n0 + tx * 8 + c];
#pragma unroll
    for (int j = 0; j < 4; j++) {
        float* op = O + (size_t)(m0 + ty * 4 + j) * H_ + n0 + tx * 8;
        float4 o0, o1;
        o0.x = acc[j][0] + bv[0]; o0.y = acc[j][1] + bv[1];
        o0.z = acc[j][2] + bv[2]; o0.w = acc[j][3] + bv[3];
        o1.x = acc[j][4] + bv[4]; o1.y = acc[j][5] + bv[5];
        o1.z = acc[j][6] + bv[6]; o1.w = acc[j][7] + bv[7];
        *(float4*)op = o0;
        *(float4*)(op + 4) = o1;
    }
}

// ---------------------------------------------------------------------------
// Launch.  Inputs per metadata order:
// 0 attn_input, 1 attention_mask(unused: softmax-invariant), 2 Wq, 3 bq,
// 4 Wk, 5 bk, 6 Wv, 7 bv, 8 Wo, 9 bo, 10 bias
// ---------------------------------------------------------------------------
extern "C" void kernel_launch(void* const* d_in, const int* in_sizes, int n_in,
                              void* d_out, int out_size)
{
    (void)in_sizes; (void)n_in; (void)out_size;
    const float* X    = (const float*)d_in[0];
    const float* Wq   = (const float*)d_in[2];
    const float* bq   = (const float*)d_in[3];
    const float* Wk   = (const float*)d_in[4];
    const float* bk   = (const float*)d_in[5];
    const float* Wv   = (const float*)d_in[6];
    const float* bv   = (const float*)d_in[7];
    const float* Wo   = (const float*)d_in[8];
    const float* bo   = (const float*)d_in[9];
    const float* bias = (const float*)d_in[10];
    float* O = (float*)d_out;

    qkv_gemm<<<dim3(128, 3, 1), 256>>>(X, Wq, bq, Wk, bk, Wv, bv);

    cudaFuncSetAttribute(attn_kernel,
                         cudaFuncAttributeMaxDynamicSharedMemorySize,
                         ATTN_SMEM_BYTES);
    attn_kernel<<<256, 256, ATTN_SMEM_BYTES>>>(bias);

    outproj_kernel<<<dim3(256, 8, 1), 256>>>(Wo, bo, O);
}

// round 8
// speedup vs baseline: 1.7465x; 1.7465x over previous
#include <cuda_runtime.h>
#include <cuda_bf16.h>
#include <cstdint>

#define B_ 8
#define T_ 2048
#define H_ 1024
#define P_ 64
#define BT_ (B_ * T_)

// Scratch (no cudaMalloc allowed)
__device__ float g_q[BT_ * P_];
__device__ float g_k[BT_ * P_];
__device__ float g_v[BT_ * P_];
__device__ float g_att[BT_ * P_];
// QKV weights transposed to [n][k] (n=192, k=1024), split bf16 hi/lo
__device__ __align__(16) __nv_bfloat16 g_wt_hi[192 * 1024];
__device__ __align__(16) __nv_bfloat16 g_wt_lo[192 * 1024];
// Wo transposed to [n][k] (n=1024, k=64), split bf16 hi/lo
__device__ __align__(16) __nv_bfloat16 g_wo_hi[1024 * 64];
__device__ __align__(16) __nv_bfloat16 g_wo_lo[1024 * 64];

// ---------------------------------------------------------------------------
// Base-ISA tensor helpers (sm_80+; compile at plain sm_103)
// ---------------------------------------------------------------------------
__device__ __forceinline__ uint32_t smem_u32(const void* p) {
    uint32_t a;
    asm("{ .reg .u64 t; cvta.to.shared.u64 t, %1; cvt.u32.u64 %0, t; }"
        : "=r"(a) : "l"(p));
    return a;
}

__device__ __forceinline__ void ldsm4(uint32_t* r, uint32_t addr) {
    asm volatile("ldmatrix.sync.aligned.m8n8.x4.shared.b16 {%0,%1,%2,%3}, [%4];"
                 : "=r"(r[0]), "=r"(r[1]), "=r"(r[2]), "=r"(r[3]) : "r"(addr));
}

__device__ __forceinline__ void mma16816(float* d, const uint32_t* a,
                                         uint32_t b0, uint32_t b1) {
    asm volatile(
        "mma.sync.aligned.m16n8k16.row.col.f32.bf16.bf16.f32 "
        "{%0,%1,%2,%3}, {%4,%5,%6,%7}, {%8,%9}, {%0,%1,%2,%3};"
        : "+f"(d[0]), "+f"(d[1]), "+f"(d[2]), "+f"(d[3])
        : "r"(a[0]), "r"(a[1]), "r"(a[2]), "r"(a[3]), "r"(b0), "r"(b1));
}

__device__ __forceinline__ uint32_t b2u(__nv_bfloat162 v) {
    union { __nv_bfloat162 b; uint32_t u; } c;
    c.b = v;
    return c.u;
}

// Split 8 fp32 into bf16 hi (uint4) and residual lo (uint4)
__device__ __forceinline__ void split8(float4 a, float4 b, uint4& hi, uint4& lo) {
    __nv_bfloat162 h01 = __floats2bfloat162_rn(a.x, a.y);
    __nv_bfloat162 h23 = __floats2bfloat162_rn(a.z, a.w);
    __nv_bfloat162 h45 = __floats2bfloat162_rn(b.x, b.y);
    __nv_bfloat162 h67 = __floats2bfloat162_rn(b.z, b.w);
    __nv_bfloat162 l01 = __floats2bfloat162_rn(a.x - __low2float(h01), a.y - __high2float(h01));
    __nv_bfloat162 l23 = __floats2bfloat162_rn(a.z - __low2float(h23), a.w - __high2float(h23));
    __nv_bfloat162 l45 = __floats2bfloat162_rn(b.x - __low2float(h45), b.y - __high2float(h45));
    __nv_bfloat162 l67 = __floats2bfloat162_rn(b.z - __low2float(h67), b.w - __high2float(h67));
    hi = make_uint4(b2u(h01), b2u(h23), b2u(h45), b2u(h67));
    lo = make_uint4(b2u(l01), b2u(l23), b2u(l45), b2u(l67));
}

// ---------------------------------------------------------------------------
// Prep: transpose + bf16-split weights
// ---------------------------------------------------------------------------
__global__ void prep_w(const float* __restrict__ Wq, const float* __restrict__ Wk,
                       const float* __restrict__ Wv) {
    int n = blockIdx.x;                 // 0..191
    const float* W = (n < 64) ? Wq : ((n < 128) ? Wk : Wv);
    int col = n & 63;
    for (int k = threadIdx.x; k < H_; k += 256) {
        float w = W[(size_t)k * P_ + col];
        __nv_bfloat16 h = __float2bfloat16_rn(w);
        g_wt_hi[(size_t)n * H_ + k] = h;
        g_wt_lo[(size_t)n * H_ + k] = __float2bfloat16_rn(w - __bfloat162float(h));
    }
}

__global__ void prep_wo(const float* __restrict__ Wo) {
    int idx = blockIdx.x * 256 + threadIdx.x;   // 0..65535
    int k = idx >> 10;                          // 0..63
    int n = idx & 1023;                         // 0..1023 (coalesced read)
    float w = Wo[(size_t)k * H_ + n];
    __nv_bfloat16 h = __float2bfloat16_rn(w);
    g_wo_hi[(size_t)n * P_ + k] = h;
    g_wo_lo[(size_t)n * P_ + k] = __float2bfloat16_rn(w - __bfloat162float(h));
}

// ---------------------------------------------------------------------------
// Kernel 1: fused QKV projection via mma.sync (bf16 split, 3 products)
// BM=64, BN=192, BK=32.  8 warps (2m x 4n), warp tile 32x48.
// smem: [0:768) bias | [1024 + s*40960): Ahi 5120 | Alo 5120 | Bhi 15360 | Blo 15360
// Row strides 80B -> conflict-free ldmatrix (20-word steps cover all banks).
// ---------------------------------------------------------------------------
#define QKV_STAGE 40960
#define QKV_AH 0
#define QKV_AL 5120
#define QKV_BH 10240
#define QKV_BL 25600
#define QKV_SMEM (1024 + 2 * QKV_STAGE)

__global__ __launch_bounds__(256) void qkv_mma(
    const float* __restrict__ X,
    const float* __restrict__ bq, const float* __restrict__ bk,
    const float* __restrict__ bv)
{
    extern __shared__ char smem[];
    const uint32_t sb = smem_u32(smem);
    const int tid = threadIdx.x, lane = tid & 31, wid = tid >> 5;
    const int wm = wid >> 2, wn = wid & 3;
    const int m0 = blockIdx.x * 64;

    float* bias_s = (float*)smem;
    if (tid < 192)
        bias_s[tid] = (tid < 64) ? bq[tid] : ((tid < 128) ? bk[tid - 64] : bv[tid - 128]);

    const int a_row = tid >> 2;
    const int a_seg = (tid & 3) * 8;            // k element offset
    const float* Xrow = X + (size_t)(m0 + a_row) * H_ + a_seg;

    const uint32_t a_off = (uint32_t)((wm * 32 + (lane & 15)) * 80 + (lane & 16));
    const uint32_t b_off = (uint32_t)((wn * 48 + (lane & 7) + ((lane & 16) >> 1)) * 80
                                      + ((lane & 8) << 1));

    float4 ar0, ar1;
    uint4 brh[3], brl[3];

    float acc[2][6][4];
#pragma unroll
    for (int i = 0; i < 2; i++)
#pragma unroll
        for (int j = 0; j < 6; j++)
#pragma unroll
            for (int c = 0; c < 4; c++) acc[i][j][c] = 0.f;

#define QKV_LDG(c) do {                                                          \
    int k0 = (c) * 32;                                                           \
    ar0 = *(const float4*)(Xrow + k0);                                           \
    ar1 = *(const float4*)(Xrow + k0 + 4);                                       \
    _Pragma("unroll")                                                            \
    for (int i = 0; i < 3; i++) {                                                \
        int idx = tid + i * 256; int n = idx >> 2, sg = idx & 3;                 \
        brh[i] = *(const uint4*)(g_wt_hi + (size_t)n * H_ + k0 + sg * 8);        \
        brl[i] = *(const uint4*)(g_wt_lo + (size_t)n * H_ + k0 + sg * 8);        \
    } } while (0)

#define QKV_STS(s) do {                                                          \
    char* bp = smem + 1024 + (s) * QKV_STAGE;                                    \
    uint4 hi, lo; split8(ar0, ar1, hi, lo);                                      \
    *(uint4*)(bp + QKV_AH + a_row * 80 + a_seg * 2) = hi;                        \
    *(uint4*)(bp + QKV_AL + a_row * 80 + a_seg * 2) = lo;                        \
    _Pragma("unroll")                                                            \
    for (int i = 0; i < 3; i++) {                                                \
        int idx = tid + i * 256; int n = idx >> 2, sg = idx & 3;                 \
        *(uint4*)(bp + QKV_BH + n * 80 + sg * 16) = brh[i];                      \
        *(uint4*)(bp + QKV_BL + n * 80 + sg * 16) = brl[i];                      \
    } } while (0)

    QKV_LDG(0);
    QKV_STS(0);
    __syncthreads();

    for (int c = 0; c < 32; ++c) {
        const int s = c & 1;
        if (c < 31) QKV_LDG(c + 1);
        const uint32_t base = sb + 1024 + s * QKV_STAGE;
#pragma unroll
        for (int ks = 0; ks < 2; ++ks) {
            uint32_t ah[2][4], al[2][4];
            ldsm4(ah[0], base + QKV_AH + a_off + ks * 32);
            ldsm4(ah[1], base + QKV_AH + a_off + 1280 + ks * 32);
            ldsm4(al[0], base + QKV_AL + a_off + ks * 32);
            ldsm4(al[1], base + QKV_AL + a_off + 1280 + ks * 32);
#pragma unroll
            for (int np = 0; np < 3; ++np) {
                uint32_t bh[4], bl[4];
                ldsm4(bh, base + QKV_BH + b_off + np * 1280 + ks * 32);
                ldsm4(bl, base + QKV_BL + b_off + np * 1280 + ks * 32);
#pragma unroll
                for (int h = 0; h < 2; ++h) {
                    const int nt = np * 2 + h;
                    mma16816(acc[0][nt], ah[0], bh[2 * h], bh[2 * h + 1]);
                    mma16816(acc[0][nt], ah[0], bl[2 * h], bl[2 * h + 1]);
                    mma16816(acc[0][nt], al[0], bh[2 * h], bh[2 * h + 1]);
                    mma16816(acc[1][nt], ah[1], bh[2 * h], bh[2 * h + 1]);
                    mma16816(acc[1][nt], ah[1], bl[2 * h], bl[2 * h + 1]);
                    mma16816(acc[1][nt], al[1], bh[2 * h], bh[2 * h + 1]);
                }
            }
        }
        if (c < 31) { QKV_STS(s ^ 1); __syncthreads(); }
    }

    // Epilogue: d frag (l>>2, 2(l&3)) / +8 rows; add bias; write Q/K/V
    const int r0 = m0 + wm * 32 + (lane >> 2);
#pragma unroll
    for (int mt = 0; mt < 2; ++mt)
#pragma unroll
        for (int nt = 0; nt < 6; ++nt) {
            int n = wn * 48 + nt * 8 + (lane & 3) * 2;
            float* out = (n < 64) ? g_q : ((n < 128) ? g_k : g_v);
            int cn = n & 63;
            int row = r0 + mt * 16;
            float b0 = bias_s[n], b1 = bias_s[n + 1];
            *(float2*)(out + (size_t)row * P_ + cn) =
                make_float2(acc[mt][nt][0] + b0, acc[mt][nt][1] + b1);
            *(float2*)(out + (size_t)(row + 8) * P_ + cn) =
                make_float2(acc[mt][nt][2] + b0, acc[mt][nt][3] + b1);
        }
}

// ---------------------------------------------------------------------------
// Kernel 2: banded attention (unchanged — exact band-129 softmax)
// ---------------------------------------------------------------------------
#define KSTR 66
#define ATTN_SMEM_FLOATS (192 * KSTR * 2 + 64 * KSTR + 132 + 8 * 132)
#define ATTN_SMEM_BYTES  (ATTN_SMEM_FLOATS * 4)

__global__ __launch_bounds__(256) void attn_kernel(const float* __restrict__ biasg)
{
    extern __shared__ float sm[];
    float* Ks     = sm;
    float* Vs     = sm + 192 * KSTR;
    float* Qs     = sm + 2 * 192 * KSTR;
    float* bias_s = Qs + 64 * KSTR;
    float* probs  = bias_s + 132;

    const int tid = threadIdx.x;
    const int b   = blockIdx.x >> 5;
    const int t0  = (blockIdx.x & 31) << 6;

    const float* Kg = g_k + (size_t)b * T_ * P_;
    const float* Vg = g_v + (size_t)b * T_ * P_;
    const float* Qg = g_q + ((size_t)b * T_ + t0) * P_;

    for (int idx = tid; idx < 192 * 16; idx += 256) {
        int jj = idx >> 4;
        int c4 = (idx & 15) << 2;
        int j  = t0 - 64 + jj;
        float4 kv = make_float4(0.f, 0.f, 0.f, 0.f);
        float4 vv = make_float4(0.f, 0.f, 0.f, 0.f);
        if (j >= 0 && j < T_) {
            kv = *(const float4*)(Kg + (size_t)j * P_ + c4);
            vv = *(const float4*)(Vg + (size_t)j * P_ + c4);
        }
        float* kd = Ks + jj * KSTR + c4;
        kd[0] = kv.x; kd[1] = kv.y; kd[2] = kv.z; kd[3] = kv.w;
        float* vd = Vs + jj * KSTR + c4;
        vd[0] = vv.x; vd[1] = vv.y; vd[2] = vv.z; vd[3] = vv.w;
    }
    for (int idx = tid; idx < 64 * 16; idx += 256) {
        int r  = idx >> 4;
        int c4 = (idx & 15) << 2;
        float4 qv = *(const float4*)(Qg + (size_t)r * P_ + c4);
        float* qd = Qs + r * KSTR + c4;
        qd[0] = qv.x; qd[1] = qv.y; qd[2] = qv.z; qd[3] = qv.w;
    }
    for (int d = tid; d < 132; d += 256)
        bias_s[d] = (d <= 128) ? biasg[1984 + d] : 0.f;
    __syncthreads();

    const int w    = tid >> 5;
    const int lane = tid & 31;
    float* pw = probs + w * 132;

    for (int rr = 0; rr < 8; rr++) {
        const int r = w * 8 + rr;
        const int t = t0 + r;
        const float2* qr = (const float2*)(Qs + r * KSTR);

        float sc[5];
#pragma unroll
        for (int c = 0; c < 5; c++) {
            int d  = c * 32 + lane;
            int jj = r + d;
            int j  = t0 - 64 + jj;
            float s = -1e30f;
            if (d <= 128 && j >= 0 && j < T_) {
                const float2* kr = (const float2*)(Ks + jj * KSTR);
                float dot = 0.f;
#pragma unroll
                for (int p = 0; p < 32; p++) {
                    float2 qa = qr[p], ka = kr[p];
                    dot += qa.x * ka.x + qa.y * ka.y;
                }
                s = dot * 0.125f + bias_s[d];
            }
            sc[c] = s;
        }
        float mx = sc[0];
#pragma unroll
        for (int c = 1; c < 5; c++) mx = fmaxf(mx, sc[c]);
#pragma unroll
        for (int off = 16; off > 0; off >>= 1)
            mx = fmaxf(mx, __shfl_xor_sync(0xffffffffu, mx, off));
        float ssum = 0.f;
#pragma unroll
        for (int c = 0; c < 5; c++) {
            float e = (sc[c] > -1e29f) ? __expf(sc[c] - mx) : 0.f;
            sc[c] = e;
            ssum += e;
        }
#pragma unroll
        for (int off = 16; off > 0; off >>= 1)
            ssum += __shfl_xor_sync(0xffffffffu, ssum, off);
        float inv = 1.f / ssum;
#pragma unroll
        for (int c = 0; c < 5; c++) {
            int d = c * 32 + lane;
            if (d <= 128) pw[d] = sc[c] * inv;
        }
        __syncwarp();

        float ox = 0.f, oy = 0.f;
#pragma unroll 4
        for (int d = 0; d < 129; d++) {
            float pb = pw[d];
            const float2* vr = (const float2*)(Vs + (r + d) * KSTR);
            float2 vv = vr[lane];
            ox += pb * vv.x;
            oy += pb * vv.y;
        }
        float2* ob = (float2*)(g_att + ((size_t)b * T_ + t) * P_);
        ob[lane] = make_float2(ox, oy);
        __syncwarp();
    }
}

// ---------------------------------------------------------------------------
// Kernel 3: output projection via mma.sync.  BM=64, BN=128, K=64 (one shot).
// 8 warps 2m x 4n, warp tile 32x32.  Row stride 144B (conflict-free ldmatrix).
// ---------------------------------------------------------------------------
#define OP_AH 0
#define OP_AL 9216
#define OP_BH 18432
#define OP_BL 36864
#define OP_SMEM 55296

__global__ __launch_bounds__(256) void outproj_mma(
    const float* __restrict__ bo, float* __restrict__ O)
{
    extern __shared__ char smem[];
    const uint32_t sb = smem_u32(smem);
    const int tid = threadIdx.x, lane = tid & 31, wid = tid >> 5;
    const int wm = wid >> 2, wn = wid & 3;
    const int m0 = blockIdx.x * 64;
    const int n0 = blockIdx.y * 128;

    // Stage A (g_att 64x64 fp32 -> hi/lo)
    {
        int row = tid >> 2, ks = (tid & 3) * 16;
        const float* ap = g_att + (size_t)(m0 + row) * P_ + ks;
        float4 f0 = *(const float4*)(ap + 0);
        float4 f1 = *(const float4*)(ap + 4);
        float4 f2 = *(const float4*)(ap + 8);
        float4 f3 = *(const float4*)(ap + 12);
        uint4 hi0, lo0, hi1, lo1;
        split8(f0, f1, hi0, lo0);
        split8(f2, f3, hi1, lo1);
        char* bp = smem;
        *(uint4*)(bp + OP_AH + row * 144 + ks * 2)      = hi0;
        *(uint4*)(bp + OP_AH + row * 144 + ks * 2 + 16) = hi1;
        *(uint4*)(bp + OP_AL + row * 144 + ks * 2)      = lo0;
        *(uint4*)(bp + OP_AL + row * 144 + ks * 2 + 16) = lo1;
    }
    // Stage B (g_wo [n][64] bf16)
#pragma unroll
    for (int i = 0; i < 4; i++) {
        int idx = tid + i * 256;
        int n = idx >> 3, sg = idx & 7;
        *(uint4*)(smem + OP_BH + n * 144 + sg * 16) =
            *(const uint4*)(g_wo_hi + (size_t)(n0 + n) * P_ + sg * 8);
        *(uint4*)(smem + OP_BL + n * 144 + sg * 16) =
            *(const uint4*)(g_wo_lo + (size_t)(n0 + n) * P_ + sg * 8);
    }
    __syncthreads();

    const uint32_t a_off = (uint32_t)((wm * 32 + (lane & 15)) * 144 + (lane & 16));
    const uint32_t b_off = (uint32_t)((wn * 32 + (lane & 7) + ((lane & 16) >> 1)) * 144
                                      + ((lane & 8) << 1));

    float acc[2][4][4];
#pragma unroll
    for (int i = 0; i < 2; i++)
#pragma unroll
        for (int j = 0; j < 4; j++)
#pragma unroll
            for (int c = 0; c < 4; c++) acc[i][j][c] = 0.f;

#pragma unroll
    for (int ks = 0; ks < 4; ++ks) {
        uint32_t ah[2][4], al[2][4];
        ldsm4(ah[0], sb + OP_AH + a_off + ks * 32);
        ldsm4(ah[1], sb + OP_AH + a_off + 2304 + ks * 32);
        ldsm4(al[0], sb + OP_AL + a_off + ks * 32);
        ldsm4(al[1], sb + OP_AL + a_off + 2304 + ks * 32);
#pragma unroll
        for (int np = 0; np < 2; ++np) {
            uint32_t bh[4], bl[4];
            ldsm4(bh, sb + OP_BH + b_off + np * 2304 + ks * 32);
            ldsm4(bl, sb + OP_BL + b_off + np * 2304 + ks * 32);
#pragma unroll
            for (int h = 0; h < 2; ++h) {
                const int nt = np * 2 + h;
                mma16816(acc[0][nt], ah[0], bh[2 * h], bh[2 * h + 1]);
                mma16816(acc[0][nt], ah[0], bl[2 * h], bl[2 * h + 1]);
                mma16816(acc[0][nt], al[0], bh[2 * h], bh[2 * h + 1]);
                mma16816(acc[1][nt], ah[1], bh[2 * h], bh[2 * h + 1]);
                mma16816(acc[1][nt], ah[1], bl[2 * h], bl[2 * h + 1]);
                mma16816(acc[1][nt], al[1], bh[2 * h], bh[2 * h + 1]);
            }
        }
    }

    const int r0 = m0 + wm * 32 + (lane >> 2);
#pragma unroll
    for (int mt = 0; mt < 2; ++mt)
#pragma unroll
        for (int nt = 0; nt < 4; ++nt) {
            int n = n0 + wn * 32 + nt * 8 + (lane & 3) * 2;
            int row = r0 + mt * 16;
            float b0 = __ldg(bo + n), b1 = __ldg(bo + n + 1);
            *(float2*)(O + (size_t)row * H_ + n) =
                make_float2(acc[mt][nt][0] + b0, acc[mt][nt][1] + b1);
            *(float2*)(O + (size_t)(row + 8) * H_ + n) =
                make_float2(acc[mt][nt][2] + b0, acc[mt][nt][3] + b1);
        }
}

// ---------------------------------------------------------------------------
// Launch
// ---------------------------------------------------------------------------
extern "C" void kernel_launch(void* const* d_in, const int* in_sizes, int n_in,
                              void* d_out, int out_size)
{
    (void)in_sizes; (void)n_in; (void)out_size;
    const float* X    = (const float*)d_in[0];
    const float* Wq   = (const float*)d_in[2];
    const float* bq   = (const float*)d_in[3];
    const float* Wk   = (const float*)d_in[4];
    const float* bk   = (const float*)d_in[5];
    const float* Wv   = (const float*)d_in[6];
    const float* bv   = (const float*)d_in[7];
    const float* Wo   = (const float*)d_in[8];
    const float* bo   = (const float*)d_in[9];
    const float* bias = (const float*)d_in[10];
    float* O = (float*)d_out;

    prep_w<<<192, 256>>>(Wq, Wk, Wv);
    prep_wo<<<256, 256>>>(Wo);

    cudaFuncSetAttribute(qkv_mma, cudaFuncAttributeMaxDynamicSharedMemorySize,
                         QKV_SMEM);
    qkv_mma<<<256, 256, QKV_SMEM>>>(X, bq, bk, bv);

    cudaFuncSetAttribute(attn_kernel, cudaFuncAttributeMaxDynamicSharedMemorySize,
                         ATTN_SMEM_BYTES);
    attn_kernel<<<256, 256, ATTN_SMEM_BYTES>>>(bias);

    cudaFuncSetAttribute(outproj_mma, cudaFuncAttributeMaxDynamicSharedMemorySize,
                         OP_SMEM);
    outproj_mma<<<dim3(256, 8, 1), 256, OP_SMEM>>>(bo, O);
}

// round 10
// speedup vs baseline: 2.4292x; 1.3909x over previous
#include <cuda_runtime.h>
#include <cuda_bf16.h>
#include <cstdint>

#define B_ 8
#define T_ 2048
#define H_ 1024
#define P_ 64
#define BT_ (B_ * T_)

// Scratch (no cudaMalloc allowed)
__device__ float g_q[BT_ * P_];
__device__ float g_k[BT_ * P_];
__device__ float g_v[BT_ * P_];
__device__ float g_att[BT_ * P_];
// QKV weights transposed to [n][k] (n=192, k=1024), split bf16 hi/lo
__device__ __align__(16) __nv_bfloat16 g_wt_hi[192 * 1024];
__device__ __align__(16) __nv_bfloat16 g_wt_lo[192 * 1024];
// Wo transposed to [n][k] (n=1024, k=64), split bf16 hi/lo
__device__ __align__(16) __nv_bfloat16 g_wo_hi[1024 * 64];
__device__ __align__(16) __nv_bfloat16 g_wo_lo[1024 * 64];

// ---------------------------------------------------------------------------
// Base-ISA tensor helpers (sm_80+; compile at plain sm_103)
// ---------------------------------------------------------------------------
__device__ __forceinline__ uint32_t smem_u32(const void* p) {
    uint32_t a;
    asm("{ .reg .u64 t; cvta.to.shared.u64 t, %1; cvt.u32.u64 %0, t; }"
        : "=r"(a) : "l"(p));
    return a;
}

__device__ __forceinline__ void ldsm4(uint32_t* r, uint32_t addr) {
    asm volatile("ldmatrix.sync.aligned.m8n8.x4.shared.b16 {%0,%1,%2,%3}, [%4];"
                 : "=r"(r[0]), "=r"(r[1]), "=r"(r[2]), "=r"(r[3]) : "r"(addr));
}

__device__ __forceinline__ void mma16816(float* d, const uint32_t* a,
                                         uint32_t b0, uint32_t b1) {
    asm volatile(
        "mma.sync.aligned.m16n8k16.row.col.f32.bf16.bf16.f32 "
        "{%0,%1,%2,%3}, {%4,%5,%6,%7}, {%8,%9}, {%0,%1,%2,%3};"
        : "+f"(d[0]), "+f"(d[1]), "+f"(d[2]), "+f"(d[3])
        : "r"(a[0]), "r"(a[1]), "r"(a[2]), "r"(a[3]), "r"(b0), "r"(b1));
}

__device__ __forceinline__ uint32_t b2u(__nv_bfloat162 v) {
    union { __nv_bfloat162 b; uint32_t u; } c;
    c.b = v;
    return c.u;
}

// Split 8 fp32 into bf16 hi (uint4) and residual lo (uint4)
__device__ __forceinline__ void split8(float4 a, float4 b, uint4& hi, uint4& lo) {
    __nv_bfloat162 h01 = __floats2bfloat162_rn(a.x, a.y);
    __nv_bfloat162 h23 = __floats2bfloat162_rn(a.z, a.w);
    __nv_bfloat162 h45 = __floats2bfloat162_rn(b.x, b.y);
    __nv_bfloat162 h67 = __floats2bfloat162_rn(b.z, b.w);
    __nv_bfloat162 l01 = __floats2bfloat162_rn(a.x - __low2float(h01), a.y - __high2float(h01));
    __nv_bfloat162 l23 = __floats2bfloat162_rn(a.z - __low2float(h23), a.w - __high2float(h23));
    __nv_bfloat162 l45 = __floats2bfloat162_rn(b.x - __low2float(h45), b.y - __high2float(h45));
    __nv_bfloat162 l67 = __floats2bfloat162_rn(b.z - __low2float(h67), b.w - __high2float(h67));
    hi = make_uint4(b2u(h01), b2u(h23), b2u(h45), b2u(h67));
    lo = make_uint4(b2u(l01), b2u(l23), b2u(l45), b2u(l67));
}

// Split 4 fp32 into bf16 hi (uint2) and residual lo (uint2)
__device__ __forceinline__ void split4(float4 v, uint2& hi, uint2& lo) {
    __nv_bfloat162 h01 = __floats2bfloat162_rn(v.x, v.y);
    __nv_bfloat162 h23 = __floats2bfloat162_rn(v.z, v.w);
    __nv_bfloat162 l01 = __floats2bfloat162_rn(v.x - __low2float(h01), v.y - __high2float(h01));
    __nv_bfloat162 l23 = __floats2bfloat162_rn(v.z - __low2float(h23), v.w - __high2float(h23));
    hi = make_uint2(b2u(h01), b2u(h23));
    lo = make_uint2(b2u(l01), b2u(l23));
}

// ---------------------------------------------------------------------------
// Prep: transpose + bf16-split weights
// ---------------------------------------------------------------------------
__global__ void prep_w(const float* __restrict__ Wq, const float* __restrict__ Wk,
                       const float* __restrict__ Wv) {
    int n = blockIdx.x;                 // 0..191
    const float* W = (n < 64) ? Wq : ((n < 128) ? Wk : Wv);
    int col = n & 63;
    for (int k = threadIdx.x; k < H_; k += 256) {
        float w = W[(size_t)k * P_ + col];
        __nv_bfloat16 h = __float2bfloat16_rn(w);
        g_wt_hi[(size_t)n * H_ + k] = h;
        g_wt_lo[(size_t)n * H_ + k] = __float2bfloat16_rn(w - __bfloat162float(h));
    }
}

__global__ void prep_wo(const float* __restrict__ Wo) {
    int idx = blockIdx.x * 256 + threadIdx.x;   // 0..65535
    int k = idx >> 10;                          // 0..63
    int n = idx & 1023;                         // 0..1023 (coalesced read)
    float w = Wo[(size_t)k * H_ + n];
    __nv_bfloat16 h = __float2bfloat16_rn(w);
    g_wo_hi[(size_t)n * P_ + k] = h;
    g_wo_lo[(size_t)n * P_ + k] = __float2bfloat16_rn(w - __bfloat162float(h));
}

// ---------------------------------------------------------------------------
// Kernel 1: fused QKV projection via mma.sync (bf16 split, 3 products)
// (unchanged from R8 — passed at rel_err 7.7e-6)
// ---------------------------------------------------------------------------
#define QKV_STAGE 40960
#define QKV_AH 0
#define QKV_AL 5120
#define QKV_BH 10240
#define QKV_BL 25600
#define QKV_SMEM (1024 + 2 * QKV_STAGE)

__global__ __launch_bounds__(256) void qkv_mma(
    const float* __restrict__ X,
    const float* __restrict__ bq, const float* __restrict__ bk,
    const float* __restrict__ bv)
{
    extern __shared__ char smem[];
    const uint32_t sb = smem_u32(smem);
    const int tid = threadIdx.x, lane = tid & 31, wid = tid >> 5;
    const int wm = wid >> 2, wn = wid & 3;
    const int m0 = blockIdx.x * 64;

    float* bias_s = (float*)smem;
    if (tid < 192)
        bias_s[tid] = (tid < 64) ? bq[tid] : ((tid < 128) ? bk[tid - 64] : bv[tid - 128]);

    const int a_row = tid >> 2;
    const int a_seg = (tid & 3) * 8;
    const float* Xrow = X + (size_t)(m0 + a_row) * H_ + a_seg;

    const uint32_t a_off = (uint32_t)((wm * 32 + (lane & 15)) * 80 + (lane & 16));
    const uint32_t b_off = (uint32_t)((wn * 48 + (lane & 7) + ((lane & 16) >> 1)) * 80
                                      + ((lane & 8) << 1));

    float4 ar0, ar1;
    uint4 brh[3], brl[3];

    float acc[2][6][4];
#pragma unroll
    for (int i = 0; i < 2; i++)
#pragma unroll
        for (int j = 0; j < 6; j++)
#pragma unroll
            for (int c = 0; c < 4; c++) acc[i][j][c] = 0.f;

#define QKV_LDG(c) do {                                                          \
    int k0 = (c) * 32;                                                           \
    ar0 = *(const float4*)(Xrow + k0);                                           \
    ar1 = *(const float4*)(Xrow + k0 + 4);                                       \
    _Pragma("unroll")                                                            \
    for (int i = 0; i < 3; i++) {                                                \
        int idx = tid + i * 256; int n = idx >> 2, sg = idx & 3;                 \
        brh[i] = *(const uint4*)(g_wt_hi + (size_t)n * H_ + k0 + sg * 8);        \
        brl[i] = *(const uint4*)(g_wt_lo + (size_t)n * H_ + k0 + sg * 8);        \
    } } while (0)

#define QKV_STS(s) do {                                                          \
    char* bp = smem + 1024 + (s) * QKV_STAGE;                                    \
    uint4 hi, lo; split8(ar0, ar1, hi, lo);                                      \
    *(uint4*)(bp + QKV_AH + a_row * 80 + a_seg * 2) = hi;                        \
    *(uint4*)(bp + QKV_AL + a_row * 80 + a_seg * 2) = lo;                        \
    _Pragma("unroll")                                                            \
    for (int i = 0; i < 3; i++) {                                                \
        int idx = tid + i * 256; int n = idx >> 2, sg = idx & 3;                 \
        *(uint4*)(bp + QKV_BH + n * 80 + sg * 16) = brh[i];                      \
        *(uint4*)(bp + QKV_BL + n * 80 + sg * 16) = brl[i];                      \
    } } while (0)

    QKV_LDG(0);
    QKV_STS(0);
    __syncthreads();

    for (int c = 0; c < 32; ++c) {
        const int s = c & 1;
        if (c < 31) QKV_LDG(c + 1);
        const uint32_t base = sb + 1024 + s * QKV_STAGE;
#pragma unroll
        for (int ks = 0; ks < 2; ++ks) {
            uint32_t ah[2][4], al[2][4];
            ldsm4(ah[0], base + QKV_AH + a_off + ks * 32);
            ldsm4(ah[1], base + QKV_AH + a_off + 1280 + ks * 32);
            ldsm4(al[0], base + QKV_AL + a_off + ks * 32);
            ldsm4(al[1], base + QKV_AL + a_off + 1280 + ks * 32);
#pragma unroll
            for (int np = 0; np < 3; ++np) {
                uint32_t bh[4], bl[4];
                ldsm4(bh, base + QKV_BH + b_off + np * 1280 + ks * 32);
                ldsm4(bl, base + QKV_BL + b_off + np * 1280 + ks * 32);
#pragma unroll
                for (int h = 0; h < 2; ++h) {
                    const int nt = np * 2 + h;
                    mma16816(acc[0][nt], ah[0], bh[2 * h], bh[2 * h + 1]);
                    mma16816(acc[0][nt], ah[0], bl[2 * h], bl[2 * h + 1]);
                    mma16816(acc[0][nt], al[0], bh[2 * h], bh[2 * h + 1]);
                    mma16816(acc[1][nt], ah[1], bh[2 * h], bh[2 * h + 1]);
                    mma16816(acc[1][nt], ah[1], bl[2 * h], bl[2 * h + 1]);
                    mma16816(acc[1][nt], al[1], bh[2 * h], bh[2 * h + 1]);
                }
            }
        }
        if (c < 31) { QKV_STS(s ^ 1); __syncthreads(); }
    }

    const int r0 = m0 + wm * 32 + (lane >> 2);
#pragma unroll
    for (int mt = 0; mt < 2; ++mt)
#pragma unroll
        for (int nt = 0; nt < 6; ++nt) {
            int n = wn * 48 + nt * 8 + (lane & 3) * 2;
            float* out = (n < 64) ? g_q : ((n < 128) ? g_k : g_v);
            int cn = n & 63;
            int row = r0 + mt * 16;
            float b0 = bias_s[n], b1 = bias_s[n + 1];
            *(float2*)(out + (size_t)row * P_ + cn) =
                make_float2(acc[mt][nt][0] + b0, acc[mt][nt][1] + b1);
            *(float2*)(out + (size_t)(row + 8) * P_ + cn) =
                make_float2(acc[mt][nt][2] + b0, acc[mt][nt][3] + b1);
        }
}

// ---------------------------------------------------------------------------
// Kernel 2: banded attention via mma.sync (flash-style, fragments resident)
// Block = (batch, 64-row query tile), 8 warps.
// Warp w: row-block rb=(w&3) (16 rows), band half h=(w>>2) (96 of 192 keys).
// S = Q@K^T (split bf16, 3 products) -> masked+bias softmax in fragments
// (cross-warp max/sum via smem) -> P repacked reg->reg into A fragments
// (C-frag of two n8 tiles == A-frag of one k16 tile) -> O = P@V via MMA
// against transposed V; partner warps sum partials; normalize at store.
// ---------------------------------------------------------------------------
#define AT_KH   0
#define AT_KL   27648
#define AT_QH   55296
#define AT_QL   64512
#define AT_VH   73728
#define AT_VL   99328
#define AT_BIAS 124928
#define AT_MAX  125696
#define AT_SUM  126208
#define AT_PART 126720
#define AT_SMEM 143616

__global__ __launch_bounds__(256) void attn_mma(const float* __restrict__ biasg)
{
    extern __shared__ char smem[];
    const uint32_t sb = smem_u32(smem);
    const int tid = threadIdx.x, lane = tid & 31, w = tid >> 5;
    const int h = w >> 2, rb = w & 3;
    const int b  = blockIdx.x >> 5;
    const int t0 = (blockIdx.x & 31) << 6;

    const float* Kg = g_k + (size_t)b * T_ * P_;
    const float* Vg = g_v + (size_t)b * T_ * P_;
    const float* Qg = g_q + ((size_t)b * T_ + t0) * P_;

    // ---- Stage K (band, [192][72] bf16 hi/lo) and V transposed ([64][200])
    for (int idx = tid; idx < 192 * 16; idx += 256) {
        int j = idx >> 4, d4 = (idx & 15) << 2;
        int jg = t0 - 64 + j;
        float4 kv = make_float4(0.f, 0.f, 0.f, 0.f);
        float4 vv = make_float4(0.f, 0.f, 0.f, 0.f);
        if (jg >= 0 && jg < T_) {
            kv = *(const float4*)(Kg + (size_t)jg * P_ + d4);
            vv = *(const float4*)(Vg + (size_t)jg * P_ + d4);
        }
        uint2 khi, klo;
        split4(kv, khi, klo);
        *(uint2*)(smem + AT_KH + j * 144 + d4 * 2) = khi;
        *(uint2*)(smem + AT_KL + j * 144 + d4 * 2) = klo;
        float vals[4] = {vv.x, vv.y, vv.z, vv.w};
#pragma unroll
        for (int i = 0; i < 4; i++) {
            int d = d4 + i;
            __nv_bfloat16 vh = __float2bfloat16_rn(vals[i]);
            *(__nv_bfloat16*)(smem + AT_VH + d * 400 + j * 2) = vh;
            *(__nv_bfloat16*)(smem + AT_VL + d * 400 + j * 2) =
                __float2bfloat16_rn(vals[i] - __bfloat162float(vh));
        }
    }
    // ---- Stage Q ([64][72] bf16 hi/lo)
    for (int idx = tid; idx < 64 * 16; idx += 256) {
        int r = idx >> 4, d4 = (idx & 15) << 2;
        float4 qv = *(const float4*)(Qg + (size_t)r * P_ + d4);
        uint2 qhi, qlo;
        split4(qv, qhi, qlo);
        *(uint2*)(smem + AT_QH + r * 144 + d4 * 2) = qhi;
        *(uint2*)(smem + AT_QL + r * 144 + d4 * 2) = qlo;
    }
    float* bias_s = (float*)(smem + AT_BIAS);
    for (int d = tid; d < 192; d += 256)
        bias_s[d] = (d <= 128) ? biasg[1984 + d] : 0.f;
    __syncthreads();

    // ---- S = Q @ K^T  (acc[nt][4], nt over 12 n8-tiles of this warp's half)
    const uint32_t a_off = (uint32_t)((rb * 16 + (lane & 15)) * 144 + (lane & 16));
    const uint32_t b_off = (uint32_t)(((lane & 7) + ((lane & 16) >> 1)) * 144
                                      + ((lane & 8) << 1));
    float acc[12][4];
#pragma unroll
    for (int nt = 0; nt < 12; nt++)
#pragma unroll
        for (int c = 0; c < 4; c++) acc[nt][c] = 0.f;

#pragma unroll
    for (int ks = 0; ks < 4; ++ks) {
        uint32_t qh[4], ql[4];
        ldsm4(qh, sb + AT_QH + a_off + ks * 32);
        ldsm4(ql, sb + AT_QL + a_off + ks * 32);
#pragma unroll
        for (int np = 0; np < 6; ++np) {
            uint32_t kb = sb + b_off + (uint32_t)((h * 96 + np * 16) * 144) + ks * 32;
            uint32_t kh4[4], kl4[4];
            ldsm4(kh4, kb + AT_KH);
            ldsm4(kl4, kb + AT_KL);
#pragma unroll
            for (int hh = 0; hh < 2; ++hh) {
                const int nt = np * 2 + hh;
                mma16816(acc[nt], qh, kh4[2 * hh], kh4[2 * hh + 1]);
                mma16816(acc[nt], qh, kl4[2 * hh], kl4[2 * hh + 1]);
                mma16816(acc[nt], ql, kh4[2 * hh], kh4[2 * hh + 1]);
            }
        }
    }

    // ---- mask + bias + softmax (rows r1, r2 live in 4-lane quads)
    const int r1 = rb * 16 + (lane >> 2);
    const int r2 = r1 + 8;
    float* smax = (float*)(smem + AT_MAX);
    float* ssum = (float*)(smem + AT_SUM);

    float m1 = -1e30f, m2v = -1e30f;
#pragma unroll
    for (int nt = 0; nt < 12; nt++) {
        int cbase = h * 96 + nt * 8 + 2 * (lane & 3);
#pragma unroll
        for (int e = 0; e < 2; e++) {
            int c = cbase + e;
            int jg = t0 - 64 + c;
            bool jv = (jg >= 0 && jg < T_);
            int rel1 = c - r1;
            bool v1 = jv && rel1 >= 0 && rel1 <= 128;
            float s1v = v1 ? fmaf(acc[nt][e], 0.125f, bias_s[rel1]) : -1e30f;
            acc[nt][e] = s1v;
            m1 = fmaxf(m1, s1v);
            int rel2 = c - r2;
            bool v2 = jv && rel2 >= 0 && rel2 <= 128;
            float s2v = v2 ? fmaf(acc[nt][2 + e], 0.125f, bias_s[rel2]) : -1e30f;
            acc[nt][2 + e] = s2v;
            m2v = fmaxf(m2v, s2v);
        }
    }
    m1  = fmaxf(m1,  __shfl_xor_sync(0xffffffffu, m1, 1));
    m1  = fmaxf(m1,  __shfl_xor_sync(0xffffffffu, m1, 2));
    m2v = fmaxf(m2v, __shfl_xor_sync(0xffffffffu, m2v, 1));
    m2v = fmaxf(m2v, __shfl_xor_sync(0xffffffffu, m2v, 2));
    if ((lane & 3) == 0) {
        smax[h * 64 + r1] = m1;
        smax[h * 64 + r2] = m2v;
    }
    __syncthreads();
    const float gm1 = fmaxf(smax[r1], smax[64 + r1]);
    const float gm2 = fmaxf(smax[r2], smax[64 + r2]);

    float su1 = 0.f, su2 = 0.f;
#pragma unroll
    for (int nt = 0; nt < 12; nt++) {
#pragma unroll
        for (int e = 0; e < 2; e++) {
            float p1 = __expf(acc[nt][e] - gm1);
            float p2 = __expf(acc[nt][2 + e] - gm2);
            acc[nt][e] = p1;
            acc[nt][2 + e] = p2;
            su1 += p1;
            su2 += p2;
        }
    }
    su1 += __shfl_xor_sync(0xffffffffu, su1, 1);
    su1 += __shfl_xor_sync(0xffffffffu, su1, 2);
    su2 += __shfl_xor_sync(0xffffffffu, su2, 1);
    su2 += __shfl_xor_sync(0xffffffffu, su2, 2);
    if ((lane & 3) == 0) {
        ssum[h * 64 + r1] = su1;
        ssum[h * 64 + r2] = su2;
    }

    // ---- P -> A fragments (reg-to-reg), split hi/lo
    uint32_t ph[24], pl[24];
#pragma unroll
    for (int nt = 0; nt < 12; nt++) {
        __nv_bfloat162 h01 = __floats2bfloat162_rn(acc[nt][0], acc[nt][1]);
        __nv_bfloat162 h23 = __floats2bfloat162_rn(acc[nt][2], acc[nt][3]);
        ph[2 * nt]     = b2u(h01);
        ph[2 * nt + 1] = b2u(h23);
        pl[2 * nt]     = b2u(__floats2bfloat162_rn(acc[nt][0] - __low2float(h01),
                                                   acc[nt][1] - __high2float(h01)));
        pl[2 * nt + 1] = b2u(__floats2bfloat162_rn(acc[nt][2] - __low2float(h23),
                                                   acc[nt][3] - __high2float(h23)));
    }
    __syncthreads();   // ssum visible; K/Q smem no longer needed

    // ---- O_partial = P @ V  over this warp's 96 keys
    const uint32_t vt_off = (uint32_t)(((lane & 7) + ((lane & 16) >> 1)) * 400
                                       + ((lane & 8) << 1) + h * 192);
    float oacc[8][4];
#pragma unroll
    for (int nt = 0; nt < 8; nt++)
#pragma unroll
        for (int c = 0; c < 4; c++) oacc[nt][c] = 0.f;

#pragma unroll
    for (int kk = 0; kk < 6; ++kk) {
        const uint32_t* aph = ph + kk * 4;
        const uint32_t* apl = pl + kk * 4;
#pragma unroll
        for (int nv = 0; nv < 4; ++nv) {
            uint32_t vb = sb + vt_off + (uint32_t)(nv * 6400) + kk * 32;
            uint32_t vh4[4], vl4[4];
            ldsm4(vh4, vb + AT_VH);
            ldsm4(vl4, vb + AT_VL);
#pragma unroll
            for (int hh = 0; hh < 2; ++hh) {
                const int nt = nv * 2 + hh;
                mma16816(oacc[nt], aph, vh4[2 * hh], vh4[2 * hh + 1]);
                mma16816(oacc[nt], aph, vl4[2 * hh], vl4[2 * hh + 1]);
                mma16816(oacc[nt], apl, vh4[2 * hh], vh4[2 * hh + 1]);
            }
        }
    }

    // ---- combine halves (h=1 stores partials; h=0 adds, normalizes, writes)
    float* part = (float*)(smem + AT_PART);   // [64][66] fp32
    if (h == 1) {
#pragma unroll
        for (int nt = 0; nt < 8; nt++) {
            int col = nt * 8 + 2 * (lane & 3);
            *(float2*)(part + r1 * 66 + col) = make_float2(oacc[nt][0], oacc[nt][1]);
            *(float2*)(part + r2 * 66 + col) = make_float2(oacc[nt][2], oacc[nt][3]);
        }
    }
    __syncthreads();
    if (h == 0) {
        const float inv1 = 1.f / (ssum[r1] + ssum[64 + r1]);
        const float inv2 = 1.f / (ssum[r2] + ssum[64 + r2]);
        float* O1 = g_att + ((size_t)b * T_ + t0 + r1) * P_;
        float* O2 = g_att + ((size_t)b * T_ + t0 + r2) * P_;
#pragma unroll
        for (int nt = 0; nt < 8; nt++) {
            int col = nt * 8 + 2 * (lane & 3);
            float2 p1 = *(float2*)(part + r1 * 66 + col);
            float2 p2 = *(float2*)(part + r2 * 66 + col);
            *(float2*)(O1 + col) = make_float2((oacc[nt][0] + p1.x) * inv1,
                                               (oacc[nt][1] + p1.y) * inv1);
            *(float2*)(O2 + col) = make_float2((oacc[nt][2] + p2.x) * inv2,
                                               (oacc[nt][3] + p2.y) * inv2);
        }
    }
}

// ---------------------------------------------------------------------------
// Kernel 3: output projection via mma.sync (unchanged from R8)
// ---------------------------------------------------------------------------
#define OP_AH 0
#define OP_AL 9216
#define OP_BH 18432
#define OP_BL 36864
#define OP_SMEM 55296

__global__ __launch_bounds__(256) void outproj_mma(
    const float* __restrict__ bo, float* __restrict__ O)
{
    extern __shared__ char smem[];
    const uint32_t sb = smem_u32(smem);
    const int tid = threadIdx.x, lane = tid & 31, wid = tid >> 5;
    const int wm = wid >> 2, wn = wid & 3;
    const int m0 = blockIdx.x * 64;
    const int n0 = blockIdx.y * 128;

    {
        int row = tid >> 2, ks = (tid & 3) * 16;
        const float* ap = g_att + (size_t)(m0 + row) * P_ + ks;
        float4 f0 = *(const float4*)(ap + 0);
        float4 f1 = *(const float4*)(ap + 4);
        float4 f2 = *(const float4*)(ap + 8);
        float4 f3 = *(const float4*)(ap + 12);
        uint4 hi0, lo0, hi1, lo1;
        split8(f0, f1, hi0, lo0);
        split8(f2, f3, hi1, lo1);
        char* bp = smem;
        *(uint4*)(bp + OP_AH + row * 144 + ks * 2)      = hi0;
        *(uint4*)(bp + OP_AH + row * 144 + ks * 2 + 16) = hi1;
        *(uint4*)(bp + OP_AL + row * 144 + ks * 2)      = lo0;
        *(uint4*)(bp + OP_AL + row * 144 + ks * 2 + 16) = lo1;
    }
#pragma unroll
    for (int i = 0; i < 4; i++) {
        int idx = tid + i * 256;
        int n = idx >> 3, sg = idx & 7;
        *(uint4*)(smem + OP_BH + n * 144 + sg * 16) =
            *(const uint4*)(g_wo_hi + (size_t)(n0 + n) * P_ + sg * 8);
        *(uint4*)(smem + OP_BL + n * 144 + sg * 16) =
            *(const uint4*)(g_wo_lo + (size_t)(n0 + n) * P_ + sg * 8);
    }
    __syncthreads();

    const uint32_t a_off = (uint32_t)((wm * 32 + (lane & 15)) * 144 + (lane & 16));
    const uint32_t b_off = (uint32_t)((wn * 32 + (lane & 7) + ((lane & 16) >> 1)) * 144
                                      + ((lane & 8) << 1));

    float acc[2][4][4];
#pragma unroll
    for (int i = 0; i < 2; i++)
#pragma unroll
        for (int j = 0; j < 4; j++)
#pragma unroll
            for (int c = 0; c < 4; c++) acc[i][j][c] = 0.f;

#pragma unroll
    for (int ks = 0; ks < 4; ++ks) {
        uint32_t ah[2][4], al[2][4];
        ldsm4(ah[0], sb + OP_AH + a_off + ks * 32);
        ldsm4(ah[1], sb + OP_AH + a_off + 2304 + ks * 32);
        ldsm4(al[0], sb + OP_AL + a_off + ks * 32);
        ldsm4(al[1], sb + OP_AL + a_off + 2304 + ks * 32);
#pragma unroll
        for (int np = 0; np < 2; ++np) {
            uint32_t bh[4], bl[4];
            ldsm4(bh, sb + OP_BH + b_off + np * 2304 + ks * 32);
            ldsm4(bl, sb + OP_BL + b_off + np * 2304 + ks * 32);
#pragma unroll
            for (int h = 0; h < 2; ++h) {
                const int nt = np * 2 + h;
                mma16816(acc[0][nt], ah[0], bh[2 * h], bh[2 * h + 1]);
                mma16816(acc[0][nt], ah[0], bl[2 * h], bl[2 * h + 1]);
                mma16816(acc[0][nt], al[0], bh[2 * h], bh[2 * h + 1]);
                mma16816(acc[1][nt], ah[1], bh[2 * h], bh[2 * h + 1]);
                mma16816(acc[1][nt], ah[1], bl[2 * h], bl[2 * h + 1]);
                mma16816(acc[1][nt], al[1], bh[2 * h], bh[2 * h + 1]);
            }
        }
    }

    const int r0 = m0 + wm * 32 + (lane >> 2);
#pragma unroll
    for (int mt = 0; mt < 2; ++mt)
#pragma unroll
        for (int nt = 0; nt < 4; ++nt) {
            int n = n0 + wn * 32 + nt * 8 + (lane & 3) * 2;
            int row = r0 + mt * 16;
            float b0 = __ldg(bo + n), b1 = __ldg(bo + n + 1);
            *(float2*)(O + (size_t)row * H_ + n) =
                make_float2(acc[mt][nt][0] + b0, acc[mt][nt][1] + b1);
            *(float2*)(O + (size_t)(row + 8) * H_ + n) =
                make_float2(acc[mt][nt][2] + b0, acc[mt][nt][3] + b1);
        }
}

// ---------------------------------------------------------------------------
// Launch
// ---------------------------------------------------------------------------
extern "C" void kernel_launch(void* const* d_in, const int* in_sizes, int n_in,
                              void* d_out, int out_size)
{
    (void)in_sizes; (void)n_in; (void)out_size;
    const float* X    = (const float*)d_in[0];
    const float* Wq   = (const float*)d_in[2];
    const float* bq   = (const float*)d_in[3];
    const float* Wk   = (const float*)d_in[4];
    const float* bk   = (const float*)d_in[5];
    const float* Wv   = (const float*)d_in[6];
    const float* bv   = (const float*)d_in[7];
    const float* Wo   = (const float*)d_in[8];
    const float* bo   = (const float*)d_in[9];
    const float* bias = (const float*)d_in[10];
    float* O = (float*)d_out;

    prep_w<<<192, 256>>>(Wq, Wk, Wv);
    prep_wo<<<256, 256>>>(Wo);

    cudaFuncSetAttribute(qkv_mma, cudaFuncAttributeMaxDynamicSharedMemorySize,
                         QKV_SMEM);
    qkv_mma<<<256, 256, QKV_SMEM>>>(X, bq, bk, bv);

    cudaFuncSetAttribute(attn_mma, cudaFuncAttributeMaxDynamicSharedMemorySize,
                         AT_SMEM);
    attn_mma<<<256, 256, AT_SMEM>>>(bias);

    cudaFuncSetAttribute(outproj_mma, cudaFuncAttributeMaxDynamicSharedMemorySize,
                         OP_SMEM);
    outproj_mma<<<dim3(256, 8, 1), 256, OP_SMEM>>>(bo, O);
}

// round 11
// speedup vs baseline: 2.5514x; 1.0503x over previous
#include <cuda_runtime.h>
#include <cuda_bf16.h>
#include <cstdint>

#define B_ 8
#define T_ 2048
#define H_ 1024
#define P_ 64
#define BT_ (B_ * T_)

// Scratch (no cudaMalloc allowed)
__device__ float g_q[BT_ * P_];
__device__ float g_k[BT_ * P_];
__device__ float g_v[BT_ * P_];
__device__ float g_att[BT_ * P_];
// QKV weights transposed to [n][k] (n=192, k=1024), split bf16 hi/lo
__device__ __align__(16) __nv_bfloat16 g_wt_hi[192 * 1024];
__device__ __align__(16) __nv_bfloat16 g_wt_lo[192 * 1024];
// Wo transposed to [n][k] (n=1024, k=64), split bf16 hi/lo
__device__ __align__(16) __nv_bfloat16 g_wo_hi[1024 * 64];
__device__ __align__(16) __nv_bfloat16 g_wo_lo[1024 * 64];

// ---------------------------------------------------------------------------
// Base-ISA tensor helpers (sm_80+; compile at plain sm_103)
// ---------------------------------------------------------------------------
__device__ __forceinline__ uint32_t smem_u32(const void* p) {
    uint32_t a;
    asm("{ .reg .u64 t; cvta.to.shared.u64 t, %1; cvt.u32.u64 %0, t; }"
        : "=r"(a) : "l"(p));
    return a;
}

__device__ __forceinline__ void ldsm4(uint32_t* r, uint32_t addr) {
    asm volatile("ldmatrix.sync.aligned.m8n8.x4.shared.b16 {%0,%1,%2,%3}, [%4];"
                 : "=r"(r[0]), "=r"(r[1]), "=r"(r[2]), "=r"(r[3]) : "r"(addr));
}

__device__ __forceinline__ void mma16816(float* d, const uint32_t* a,
                                         uint32_t b0, uint32_t b1) {
    asm volatile(
        "mma.sync.aligned.m16n8k16.row.col.f32.bf16.bf16.f32 "
        "{%0,%1,%2,%3}, {%4,%5,%6,%7}, {%8,%9}, {%0,%1,%2,%3};"
        : "+f"(d[0]), "+f"(d[1]), "+f"(d[2]), "+f"(d[3])
        : "r"(a[0]), "r"(a[1]), "r"(a[2]), "r"(a[3]), "r"(b0), "r"(b1));
}

__device__ __forceinline__ uint32_t b2u(__nv_bfloat162 v) {
    union { __nv_bfloat162 b; uint32_t u; } c;
    c.b = v;
    return c.u;
}

// Split 8 fp32 into bf16 hi (uint4) and residual lo (uint4)
__device__ __forceinline__ void split8(float4 a, float4 b, uint4& hi, uint4& lo) {
    __nv_bfloat162 h01 = __floats2bfloat162_rn(a.x, a.y);
    __nv_bfloat162 h23 = __floats2bfloat162_rn(a.z, a.w);
    __nv_bfloat162 h45 = __floats2bfloat162_rn(b.x, b.y);
    __nv_bfloat162 h67 = __floats2bfloat162_rn(b.z, b.w);
    __nv_bfloat162 l01 = __floats2bfloat162_rn(a.x - __low2float(h01), a.y - __high2float(h01));
    __nv_bfloat162 l23 = __floats2bfloat162_rn(a.z - __low2float(h23), a.w - __high2float(h23));
    __nv_bfloat162 l45 = __floats2bfloat162_rn(b.x - __low2float(h45), b.y - __high2float(h45));
    __nv_bfloat162 l67 = __floats2bfloat162_rn(b.z - __low2float(h67), b.w - __high2float(h67));
    hi = make_uint4(b2u(h01), b2u(h23), b2u(h45), b2u(h67));
    lo = make_uint4(b2u(l01), b2u(l23), b2u(l45), b2u(l67));
}

// Split 4 fp32 into bf16 hi (uint2) and residual lo (uint2)
__device__ __forceinline__ void split4(float4 v, uint2& hi, uint2& lo) {
    __nv_bfloat162 h01 = __floats2bfloat162_rn(v.x, v.y);
    __nv_bfloat162 h23 = __floats2bfloat162_rn(v.z, v.w);
    __nv_bfloat162 l01 = __floats2bfloat162_rn(v.x - __low2float(h01), v.y - __high2float(h01));
    __nv_bfloat162 l23 = __floats2bfloat162_rn(v.z - __low2float(h23), v.w - __high2float(h23));
    hi = make_uint2(b2u(h01), b2u(h23));
    lo = make_uint2(b2u(l01), b2u(l23));
}

// ---------------------------------------------------------------------------
// Prep: transpose + bf16-split weights
// ---------------------------------------------------------------------------
__global__ void prep_w(const float* __restrict__ Wq, const float* __restrict__ Wk,
                       const float* __restrict__ Wv) {
    int n = blockIdx.x;                 // 0..191
    const float* W = (n < 64) ? Wq : ((n < 128) ? Wk : Wv);
    int col = n & 63;
    for (int k = threadIdx.x; k < H_; k += 256) {
        float w = W[(size_t)k * P_ + col];
        __nv_bfloat16 h = __float2bfloat16_rn(w);
        g_wt_hi[(size_t)n * H_ + k] = h;
        g_wt_lo[(size_t)n * H_ + k] = __float2bfloat16_rn(w - __bfloat162float(h));
    }
}

__global__ void prep_wo(const float* __restrict__ Wo) {
    int idx = blockIdx.x * 256 + threadIdx.x;   // 0..65535
    int k = idx >> 10;                          // 0..63
    int n = idx & 1023;                         // 0..1023 (coalesced read)
    float w = Wo[(size_t)k * H_ + n];
    __nv_bfloat16 h = __float2bfloat16_rn(w);
    g_wo_hi[(size_t)n * P_ + k] = h;
    g_wo_lo[(size_t)n * P_ + k] = __float2bfloat16_rn(w - __bfloat162float(h));
}

// ---------------------------------------------------------------------------
// Kernel 1: fused QKV projection via mma.sync (bf16 split, 3 products)
// BM=128, BN=192, BK=32.  8 warps (2m x 4n), warp tile 64x48.
// Grid 128 -> halves weight L2 traffic vs BM=64.  Stage 51200B, 2-stage.
// ---------------------------------------------------------------------------
#define QKV_STAGE 51200
#define QKV_AH 0
#define QKV_AL 10240
#define QKV_BH 20480
#define QKV_BL 35840
#define QKV_SMEM (1024 + 2 * QKV_STAGE)   // 103424

__global__ __launch_bounds__(256) void qkv_mma(
    const float* __restrict__ X,
    const float* __restrict__ bq, const float* __restrict__ bk,
    const float* __restrict__ bv)
{
    extern __shared__ char smem[];
    const uint32_t sb = smem_u32(smem);
    const int tid = threadIdx.x, lane = tid & 31, wid = tid >> 5;
    const int wm = wid >> 2, wn = wid & 3;
    const int m0 = blockIdx.x * 128;

    float* bias_s = (float*)smem;
    if (tid < 192)
        bias_s[tid] = (tid < 64) ? bq[tid] : ((tid < 128) ? bk[tid - 64] : bv[tid - 128]);

    const int a_row = tid >> 1;                 // 0..127
    const int a_seg = (tid & 1) * 16;           // element offset 0/16
    const float* Xrow = X + (size_t)(m0 + a_row) * H_ + a_seg;

    const uint32_t a_off = (uint32_t)((wm * 64 + (lane & 15)) * 80 + (lane & 16));
    const uint32_t b_off = (uint32_t)((wn * 48 + (lane & 7) + ((lane & 16) >> 1)) * 80
                                      + ((lane & 8) << 1));

    float4 ar0, ar1, ar2, ar3;
    uint4 brh[3], brl[3];

    float acc[4][6][4];
#pragma unroll
    for (int i = 0; i < 4; i++)
#pragma unroll
        for (int j = 0; j < 6; j++)
#pragma unroll
            for (int c = 0; c < 4; c++) acc[i][j][c] = 0.f;

#define QKV_LDG(c) do {                                                          \
    int k0 = (c) * 32;                                                           \
    ar0 = *(const float4*)(Xrow + k0);                                           \
    ar1 = *(const float4*)(Xrow + k0 + 4);                                       \
    ar2 = *(const float4*)(Xrow + k0 + 8);                                       \
    ar3 = *(const float4*)(Xrow + k0 + 12);                                      \
    _Pragma("unroll")                                                            \
    for (int i = 0; i < 3; i++) {                                                \
        int idx = tid + i * 256; int n = idx >> 2, sg = idx & 3;                 \
        brh[i] = *(const uint4*)(g_wt_hi + (size_t)n * H_ + k0 + sg * 8);        \
        brl[i] = *(const uint4*)(g_wt_lo + (size_t)n * H_ + k0 + sg * 8);        \
    } } while (0)

#define QKV_STS(s) do {                                                          \
    char* bp = smem + 1024 + (s) * QKV_STAGE;                                    \
    uint4 hi0, lo0, hi1, lo1;                                                    \
    split8(ar0, ar1, hi0, lo0);                                                  \
    split8(ar2, ar3, hi1, lo1);                                                  \
    *(uint4*)(bp + QKV_AH + a_row * 80 + a_seg * 2)      = hi0;                  \
    *(uint4*)(bp + QKV_AH + a_row * 80 + a_seg * 2 + 16) = hi1;                  \
    *(uint4*)(bp + QKV_AL + a_row * 80 + a_seg * 2)      = lo0;                  \
    *(uint4*)(bp + QKV_AL + a_row * 80 + a_seg * 2 + 16) = lo1;                  \
    _Pragma("unroll")                                                            \
    for (int i = 0; i < 3; i++) {                                                \
        int idx = tid + i * 256; int n = idx >> 2, sg = idx & 3;                 \
        *(uint4*)(bp + QKV_BH + n * 80 + sg * 16) = brh[i];                      \
        *(uint4*)(bp + QKV_BL + n * 80 + sg * 16) = brl[i];                      \
    } } while (0)

    QKV_LDG(0);
    QKV_STS(0);
    __syncthreads();

    for (int c = 0; c < 32; ++c) {
        const int s = c & 1;
        if (c < 31) QKV_LDG(c + 1);
        const uint32_t base = sb + 1024 + s * QKV_STAGE;
#pragma unroll
        for (int ks = 0; ks < 2; ++ks) {
            uint32_t ah[4][4], al[4][4];
#pragma unroll
            for (int mt = 0; mt < 4; mt++) {
                ldsm4(ah[mt], base + QKV_AH + a_off + mt * 1280 + ks * 32);
                ldsm4(al[mt], base + QKV_AL + a_off + mt * 1280 + ks * 32);
            }
#pragma unroll
            for (int np = 0; np < 3; ++np) {
                uint32_t bh[4], bl[4];
                ldsm4(bh, base + QKV_BH + b_off + np * 1280 + ks * 32);
                ldsm4(bl, base + QKV_BL + b_off + np * 1280 + ks * 32);
#pragma unroll
                for (int hh = 0; hh < 2; ++hh) {
                    const int nt = np * 2 + hh;
#pragma unroll
                    for (int mt = 0; mt < 4; mt++) {
                        mma16816(acc[mt][nt], ah[mt], bh[2 * hh], bh[2 * hh + 1]);
                        mma16816(acc[mt][nt], ah[mt], bl[2 * hh], bl[2 * hh + 1]);
                        mma16816(acc[mt][nt], al[mt], bh[2 * hh], bh[2 * hh + 1]);
                    }
                }
            }
        }
        if (c < 31) { QKV_STS(s ^ 1); __syncthreads(); }
    }

    const int r0 = m0 + wm * 64 + (lane >> 2);
#pragma unroll
    for (int mt = 0; mt < 4; ++mt)
#pragma unroll
        for (int nt = 0; nt < 6; ++nt) {
            int n = wn * 48 + nt * 8 + (lane & 3) * 2;
            float* out = (n < 64) ? g_q : ((n < 128) ? g_k : g_v);
            int cn = n & 63;
            int row = r0 + mt * 16;
            float b0 = bias_s[n], b1 = bias_s[n + 1];
            *(float2*)(out + (size_t)row * P_ + cn) =
                make_float2(acc[mt][nt][0] + b0, acc[mt][nt][1] + b1);
            *(float2*)(out + (size_t)(row + 8) * P_ + cn) =
                make_float2(acc[mt][nt][2] + b0, acc[mt][nt][3] + b1);
        }
}

// ---------------------------------------------------------------------------
// Kernel 2: banded attention via mma.sync (unchanged from R10 — 28.4us)
// ---------------------------------------------------------------------------
#define AT_KH   0
#define AT_KL   27648
#define AT_QH   55296
#define AT_QL   64512
#define AT_VH   73728
#define AT_VL   99328
#define AT_BIAS 124928
#define AT_MAX  125696
#define AT_SUM  126208
#define AT_PART 126720
#define AT_SMEM 143616

__global__ __launch_bounds__(256) void attn_mma(const float* __restrict__ biasg)
{
    extern __shared__ char smem[];
    const uint32_t sb = smem_u32(smem);
    const int tid = threadIdx.x, lane = tid & 31, w = tid >> 5;
    const int h = w >> 2, rb = w & 3;
    const int b  = blockIdx.x >> 5;
    const int t0 = (blockIdx.x & 31) << 6;

    const float* Kg = g_k + (size_t)b * T_ * P_;
    const float* Vg = g_v + (size_t)b * T_ * P_;
    const float* Qg = g_q + ((size_t)b * T_ + t0) * P_;

    for (int idx = tid; idx < 192 * 16; idx += 256) {
        int j = idx >> 4, d4 = (idx & 15) << 2;
        int jg = t0 - 64 + j;
        float4 kv = make_float4(0.f, 0.f, 0.f, 0.f);
        float4 vv = make_float4(0.f, 0.f, 0.f, 0.f);
        if (jg >= 0 && jg < T_) {
            kv = *(const float4*)(Kg + (size_t)jg * P_ + d4);
            vv = *(const float4*)(Vg + (size_t)jg * P_ + d4);
        }
        uint2 khi, klo;
        split4(kv, khi, klo);
        *(uint2*)(smem + AT_KH + j * 144 + d4 * 2) = khi;
        *(uint2*)(smem + AT_KL + j * 144 + d4 * 2) = klo;
        float vals[4] = {vv.x, vv.y, vv.z, vv.w};
#pragma unroll
        for (int i = 0; i < 4; i++) {
            int d = d4 + i;
            __nv_bfloat16 vh = __float2bfloat16_rn(vals[i]);
            *(__nv_bfloat16*)(smem + AT_VH + d * 400 + j * 2) = vh;
            *(__nv_bfloat16*)(smem + AT_VL + d * 400 + j * 2) =
                __float2bfloat16_rn(vals[i] - __bfloat162float(vh));
        }
    }
    for (int idx = tid; idx < 64 * 16; idx += 256) {
        int r = idx >> 4, d4 = (idx & 15) << 2;
        float4 qv = *(const float4*)(Qg + (size_t)r * P_ + d4);
        uint2 qhi, qlo;
        split4(qv, qhi, qlo);
        *(uint2*)(smem + AT_QH + r * 144 + d4 * 2) = qhi;
        *(uint2*)(smem + AT_QL + r * 144 + d4 * 2) = qlo;
    }
    float* bias_s = (float*)(smem + AT_BIAS);
    for (int d = tid; d < 192; d += 256)
        bias_s[d] = (d <= 128) ? biasg[1984 + d] : 0.f;
    __syncthreads();

    const uint32_t a_off = (uint32_t)((rb * 16 + (lane & 15)) * 144 + (lane & 16));
    const uint32_t b_off = (uint32_t)(((lane & 7) + ((lane & 16) >> 1)) * 144
                                      + ((lane & 8) << 1));
    float acc[12][4];
#pragma unroll
    for (int nt = 0; nt < 12; nt++)
#pragma unroll
        for (int c = 0; c < 4; c++) acc[nt][c] = 0.f;

#pragma unroll
    for (int ks = 0; ks < 4; ++ks) {
        uint32_t qh[4], ql[4];
        ldsm4(qh, sb + AT_QH + a_off + ks * 32);
        ldsm4(ql, sb + AT_QL + a_off + ks * 32);
#pragma unroll
        for (int np = 0; np < 6; ++np) {
            uint32_t kb = sb + b_off + (uint32_t)((h * 96 + np * 16) * 144) + ks * 32;
            uint32_t kh4[4], kl4[4];
            ldsm4(kh4, kb + AT_KH);
            ldsm4(kl4, kb + AT_KL);
#pragma unroll
            for (int hh = 0; hh < 2; ++hh) {
                const int nt = np * 2 + hh;
                mma16816(acc[nt], qh, kh4[2 * hh], kh4[2 * hh + 1]);
                mma16816(acc[nt], qh, kl4[2 * hh], kl4[2 * hh + 1]);
                mma16816(acc[nt], ql, kh4[2 * hh], kh4[2 * hh + 1]);
            }
        }
    }

    const int r1 = rb * 16 + (lane >> 2);
    const int r2 = r1 + 8;
    float* smax = (float*)(smem + AT_MAX);
    float* ssum = (float*)(smem + AT_SUM);

    float m1 = -1e30f, m2v = -1e30f;
#pragma unroll
    for (int nt = 0; nt < 12; nt++) {
        int cbase = h * 96 + nt * 8 + 2 * (lane & 3);
#pragma unroll
        for (int e = 0; e < 2; e++) {
            int c = cbase + e;
            int jg = t0 - 64 + c;
            bool jv = (jg >= 0 && jg < T_);
            int rel1 = c - r1;
            bool v1 = jv && rel1 >= 0 && rel1 <= 128;
            float s1v = v1 ? fmaf(acc[nt][e], 0.125f, bias_s[rel1]) : -1e30f;
            acc[nt][e] = s1v;
            m1 = fmaxf(m1, s1v);
            int rel2 = c - r2;
            bool v2 = jv && rel2 >= 0 && rel2 <= 128;
            float s2v = v2 ? fmaf(acc[nt][2 + e], 0.125f, bias_s[rel2]) : -1e30f;
            acc[nt][2 + e] = s2v;
            m2v = fmaxf(m2v, s2v);
        }
    }
    m1  = fmaxf(m1,  __shfl_xor_sync(0xffffffffu, m1, 1));
    m1  = fmaxf(m1,  __shfl_xor_sync(0xffffffffu, m1, 2));
    m2v = fmaxf(m2v, __shfl_xor_sync(0xffffffffu, m2v, 1));
    m2v = fmaxf(m2v, __shfl_xor_sync(0xffffffffu, m2v, 2));
    if ((lane & 3) == 0) {
        smax[h * 64 + r1] = m1;
        smax[h * 64 + r2] = m2v;
    }
    __syncthreads();
    const float gm1 = fmaxf(smax[r1], smax[64 + r1]);
    const float gm2 = fmaxf(smax[r2], smax[64 + r2]);

    float su1 = 0.f, su2 = 0.f;
#pragma unroll
    for (int nt = 0; nt < 12; nt++) {
#pragma unroll
        for (int e = 0; e < 2; e++) {
            float p1 = __expf(acc[nt][e] - gm1);
            float p2 = __expf(acc[nt][2 + e] - gm2);
            acc[nt][e] = p1;
            acc[nt][2 + e] = p2;
            su1 += p1;
            su2 += p2;
        }
    }
    su1 += __shfl_xor_sync(0xffffffffu, su1, 1);
    su1 += __shfl_xor_sync(0xffffffffu, su1, 2);
    su2 += __shfl_xor_sync(0xffffffffu, su2, 1);
    su2 += __shfl_xor_sync(0xffffffffu, su2, 2);
    if ((lane & 3) == 0) {
        ssum[h * 64 + r1] = su1;
        ssum[h * 64 + r2] = su2;
    }

    uint32_t ph[24], pl[24];
#pragma unroll
    for (int nt = 0; nt < 12; nt++) {
        __nv_bfloat162 h01 = __floats2bfloat162_rn(acc[nt][0], acc[nt][1]);
        __nv_bfloat162 h23 = __floats2bfloat162_rn(acc[nt][2], acc[nt][3]);
        ph[2 * nt]     = b2u(h01);
        ph[2 * nt + 1] = b2u(h23);
        pl[2 * nt]     = b2u(__floats2bfloat162_rn(acc[nt][0] - __low2float(h01),
                                                   acc[nt][1] - __high2float(h01)));
        pl[2 * nt + 1] = b2u(__floats2bfloat162_rn(acc[nt][2] - __low2float(h23),
                                                   acc[nt][3] - __high2float(h23)));
    }
    __syncthreads();

    const uint32_t vt_off = (uint32_t)(((lane & 7) + ((lane & 16) >> 1)) * 400
                                       + ((lane & 8) << 1) + h * 192);
    float oacc[8][4];
#pragma unroll
    for (int nt = 0; nt < 8; nt++)
#pragma unroll
        for (int c = 0; c < 4; c++) oacc[nt][c] = 0.f;

#pragma unroll
    for (int kk = 0; kk < 6; ++kk) {
        const uint32_t* aph = ph + kk * 4;
        const uint32_t* apl = pl + kk * 4;
#pragma unroll
        for (int nv = 0; nv < 4; ++nv) {
            uint32_t vb = sb + vt_off + (uint32_t)(nv * 6400) + kk * 32;
            uint32_t vh4[4], vl4[4];
            ldsm4(vh4, vb + AT_VH);
            ldsm4(vl4, vb + AT_VL);
#pragma unroll
            for (int hh = 0; hh < 2; ++hh) {
                const int nt = nv * 2 + hh;
                mma16816(oacc[nt], aph, vh4[2 * hh], vh4[2 * hh + 1]);
                mma16816(oacc[nt], aph, vl4[2 * hh], vl4[2 * hh + 1]);
                mma16816(oacc[nt], apl, vh4[2 * hh], vh4[2 * hh + 1]);
            }
        }
    }

    float* part = (float*)(smem + AT_PART);
    if (h == 1) {
#pragma unroll
        for (int nt = 0; nt < 8; nt++) {
            int col = nt * 8 + 2 * (lane & 3);
            *(float2*)(part + r1 * 66 + col) = make_float2(oacc[nt][0], oacc[nt][1]);
            *(float2*)(part + r2 * 66 + col) = make_float2(oacc[nt][2], oacc[nt][3]);
        }
    }
    __syncthreads();
    if (h == 0) {
        const float inv1 = 1.f / (ssum[r1] + ssum[64 + r1]);
        const float inv2 = 1.f / (ssum[r2] + ssum[64 + r2]);
        float* O1 = g_att + ((size_t)b * T_ + t0 + r1) * P_;
        float* O2 = g_att + ((size_t)b * T_ + t0 + r2) * P_;
#pragma unroll
        for (int nt = 0; nt < 8; nt++) {
            int col = nt * 8 + 2 * (lane & 3);
            float2 p1 = *(float2*)(part + r1 * 66 + col);
            float2 p2 = *(float2*)(part + r2 * 66 + col);
            *(float2*)(O1 + col) = make_float2((oacc[nt][0] + p1.x) * inv1,
                                               (oacc[nt][1] + p1.y) * inv1);
            *(float2*)(O2 + col) = make_float2((oacc[nt][2] + p2.x) * inv2,
                                               (oacc[nt][3] + p2.y) * inv2);
        }
    }
}

// ---------------------------------------------------------------------------
// Kernel 3: output projection, persistent m-block.  BM=64; loops all 8
// 128-wide n-tiles with double-buffered Wo; A fragments hoisted to registers.
// Grid 256.  smem: A hi/lo 18432 | 2 x (BH 18432 + BL 18432) = 92160 B.
// ---------------------------------------------------------------------------
#define OP2_AH 0
#define OP2_AL 9216
#define OP2_B  18432
#define OP2_BSTAGE 36864
#define OP2_SMEM (18432 + 2 * 36864)   // 92160

__global__ __launch_bounds__(256) void outproj_mma(
    const float* __restrict__ bo, float* __restrict__ O)
{
    extern __shared__ char smem[];
    const uint32_t sb = smem_u32(smem);
    const int tid = threadIdx.x, lane = tid & 31, wid = tid >> 5;
    const int wm = wid >> 2, wn = wid & 3;
    const int m0 = blockIdx.x * 64;

    // Stage A (g_att 64x64 fp32 -> hi/lo), then hoist fragments to registers
    {
        int row = tid >> 2, ks = (tid & 3) * 16;
        const float* ap = g_att + (size_t)(m0 + row) * P_ + ks;
        float4 f0 = *(const float4*)(ap + 0);
        float4 f1 = *(const float4*)(ap + 4);
        float4 f2 = *(const float4*)(ap + 8);
        float4 f3 = *(const float4*)(ap + 12);
        uint4 hi0, lo0, hi1, lo1;
        split8(f0, f1, hi0, lo0);
        split8(f2, f3, hi1, lo1);
        *(uint4*)(smem + OP2_AH + row * 144 + ks * 2)      = hi0;
        *(uint4*)(smem + OP2_AH + row * 144 + ks * 2 + 16) = hi1;
        *(uint4*)(smem + OP2_AL + row * 144 + ks * 2)      = lo0;
        *(uint4*)(smem + OP2_AL + row * 144 + ks * 2 + 16) = lo1;
    }

    // Prefetch B tile 0 into registers
    uint4 brh[4], brl[4];
#define OP_LDG(nb) do {                                                          \
    int n0 = (nb) * 128;                                                         \
    _Pragma("unroll")                                                            \
    for (int i = 0; i < 4; i++) {                                                \
        int idx = tid + i * 256; int n = idx >> 3, sg = idx & 7;                 \
        brh[i] = *(const uint4*)(g_wo_hi + (size_t)(n0 + n) * P_ + sg * 8);      \
        brl[i] = *(const uint4*)(g_wo_lo + (size_t)(n0 + n) * P_ + sg * 8);      \
    } } while (0)

#define OP_STS(s) do {                                                           \
    char* bp = smem + OP2_B + (s) * OP2_BSTAGE;                                  \
    _Pragma("unroll")                                                            \
    for (int i = 0; i < 4; i++) {                                                \
        int idx = tid + i * 256; int n = idx >> 3, sg = idx & 7;                 \
        *(uint4*)(bp + n * 144 + sg * 16)         = brh[i];                      \
        *(uint4*)(bp + 18432 + n * 144 + sg * 16) = brl[i];                      \
    } } while (0)

    OP_LDG(0);
    __syncthreads();   // A staged

    // A fragments for this warp (all 4 k-steps, hi+lo): 64 regs
    const uint32_t a_off = (uint32_t)((wm * 32 + (lane & 15)) * 144 + (lane & 16));
    uint32_t ahf[4][2][4], alf[4][2][4];
#pragma unroll
    for (int ks = 0; ks < 4; ++ks)
#pragma unroll
        for (int mt = 0; mt < 2; ++mt) {
            ldsm4(ahf[ks][mt], sb + OP2_AH + a_off + mt * 2304 + ks * 32);
            ldsm4(alf[ks][mt], sb + OP2_AL + a_off + mt * 2304 + ks * 32);
        }

    OP_STS(0);
    __syncthreads();

    const uint32_t b_off = (uint32_t)((wn * 32 + (lane & 7) + ((lane & 16) >> 1)) * 144
                                      + ((lane & 8) << 1));
    const int r0 = m0 + wm * 32 + (lane >> 2);

    for (int nb = 0; nb < 8; ++nb) {
        const int s = nb & 1;
        if (nb < 7) OP_LDG(nb + 1);

        float acc[2][4][4];
#pragma unroll
        for (int i = 0; i < 2; i++)
#pragma unroll
            for (int j = 0; j < 4; j++)
#pragma unroll
                for (int c = 0; c < 4; c++) acc[i][j][c] = 0.f;

        const uint32_t bbase = sb + OP2_B + s * OP2_BSTAGE;
#pragma unroll
        for (int ks = 0; ks < 4; ++ks) {
#pragma unroll
            for (int np = 0; np < 2; ++np) {
                uint32_t bh[4], bl[4];
                ldsm4(bh, bbase + b_off + np * 2304 + ks * 32);
                ldsm4(bl, bbase + 18432 + b_off + np * 2304 + ks * 32);
#pragma unroll
                for (int hh = 0; hh < 2; ++hh) {
                    const int nt = np * 2 + hh;
#pragma unroll
                    for (int mt = 0; mt < 2; ++mt) {
                        mma16816(acc[mt][nt], ahf[ks][mt], bh[2 * hh], bh[2 * hh + 1]);
                        mma16816(acc[mt][nt], ahf[ks][mt], bl[2 * hh], bl[2 * hh + 1]);
                        mma16816(acc[mt][nt], alf[ks][mt], bh[2 * hh], bh[2 * hh + 1]);
                    }
                }
            }
        }

        // epilogue for this n-tile
        const int n0 = nb * 128;
#pragma unroll
        for (int mt = 0; mt < 2; ++mt)
#pragma unroll
            for (int nt = 0; nt < 4; ++nt) {
                int n = n0 + wn * 32 + nt * 8 + (lane & 3) * 2;
                int row = r0 + mt * 16;
                float b0 = __ldg(bo + n), b1 = __ldg(bo + n + 1);
                *(float2*)(O + (size_t)row * H_ + n) =
                    make_float2(acc[mt][nt][0] + b0, acc[mt][nt][1] + b1);
                *(float2*)(O + (size_t)(row + 8) * H_ + n) =
                    make_float2(acc[mt][nt][2] + b0, acc[mt][nt][3] + b1);
            }

        if (nb < 7) { OP_STS(s ^ 1); __syncthreads(); }
    }
}

// ---------------------------------------------------------------------------
// Launch
// ---------------------------------------------------------------------------
extern "C" void kernel_launch(void* const* d_in, const int* in_sizes, int n_in,
                              void* d_out, int out_size)
{
    (void)in_sizes; (void)n_in; (void)out_size;
    const float* X    = (const float*)d_in[0];
    const float* Wq   = (const float*)d_in[2];
    const float* bq   = (const float*)d_in[3];
    const float* Wk   = (const float*)d_in[4];
    const float* bk   = (const float*)d_in[5];
    const float* Wv   = (const float*)d_in[6];
    const float* bv   = (const float*)d_in[7];
    const float* Wo   = (const float*)d_in[8];
    const float* bo   = (const float*)d_in[9];
    const float* bias = (const float*)d_in[10];
    float* O = (float*)d_out;

    prep_w<<<192, 256>>>(Wq, Wk, Wv);
    prep_wo<<<256, 256>>>(Wo);

    cudaFuncSetAttribute(qkv_mma, cudaFuncAttributeMaxDynamicSharedMemorySize,
                         QKV_SMEM);
    qkv_mma<<<128, 256, QKV_SMEM>>>(X, bq, bk, bv);

    cudaFuncSetAttribute(attn_mma, cudaFuncAttributeMaxDynamicSharedMemorySize,
                         AT_SMEM);
    attn_mma<<<256, 256, AT_SMEM>>>(bias);

    cudaFuncSetAttribute(outproj_mma, cudaFuncAttributeMaxDynamicSharedMemorySize,
                         OP2_SMEM);
    outproj_mma<<<256, 256, OP2_SMEM>>>(bo, O);
}

// round 13
// speedup vs baseline: 2.7052x; 1.0603x over previous
#include <cuda_runtime.h>
#include <cuda_bf16.h>
#include <cstdint>

#define B_ 8
#define T_ 2048
#define H_ 1024
#define P_ 64
#define BT_ (B_ * T_)

// Scratch (no cudaMalloc allowed)
__device__ float g_q[BT_ * P_];
__device__ float g_k[BT_ * P_];
__device__ float g_v[BT_ * P_];
__device__ float g_att[BT_ * P_];
// QKV weights transposed to [n][k] (n=192, k=1024), split bf16 hi/lo
__device__ __align__(16) __nv_bfloat16 g_wt_hi[192 * 1024];
__device__ __align__(16) __nv_bfloat16 g_wt_lo[192 * 1024];
// Wo transposed to [n][k] (n=1024, k=64), split bf16 hi/lo
__device__ __align__(16) __nv_bfloat16 g_wo_hi[1024 * 64];
__device__ __align__(16) __nv_bfloat16 g_wo_lo[1024 * 64];

// ---------------------------------------------------------------------------
// Base-ISA tensor helpers (sm_80+; compile at plain sm_103)
// ---------------------------------------------------------------------------
__device__ __forceinline__ uint32_t smem_u32(const void* p) {
    uint32_t a;
    asm("{ .reg .u64 t; cvta.to.shared.u64 t, %1; cvt.u32.u64 %0, t; }"
        : "=r"(a) : "l"(p));
    return a;
}

__device__ __forceinline__ void ldsm4(uint32_t* r, uint32_t addr) {
    asm volatile("ldmatrix.sync.aligned.m8n8.x4.shared.b16 {%0,%1,%2,%3}, [%4];"
                 : "=r"(r[0]), "=r"(r[1]), "=r"(r[2]), "=r"(r[3]) : "r"(addr));
}

__device__ __forceinline__ void mma16816(float* d, const uint32_t* a,
                                         uint32_t b0, uint32_t b1) {
    asm volatile(
        "mma.sync.aligned.m16n8k16.row.col.f32.bf16.bf16.f32 "
        "{%0,%1,%2,%3}, {%4,%5,%6,%7}, {%8,%9}, {%0,%1,%2,%3};"
        : "+f"(d[0]), "+f"(d[1]), "+f"(d[2]), "+f"(d[3])
        : "r"(a[0]), "r"(a[1]), "r"(a[2]), "r"(a[3]), "r"(b0), "r"(b1));
}

__device__ __forceinline__ uint32_t b2u(__nv_bfloat162 v) {
    union { __nv_bfloat162 b; uint32_t u; } c;
    c.b = v;
    return c.u;
}

// Split 8 fp32 into bf16 hi (uint4) and residual lo (uint4)
__device__ __forceinline__ void split8(float4 a, float4 b, uint4& hi, uint4& lo) {
    __nv_bfloat162 h01 = __floats2bfloat162_rn(a.x, a.y);
    __nv_bfloat162 h23 = __floats2bfloat162_rn(a.z, a.w);
    __nv_bfloat162 h45 = __floats2bfloat162_rn(b.x, b.y);
    __nv_bfloat162 h67 = __floats2bfloat162_rn(b.z, b.w);
    __nv_bfloat162 l01 = __floats2bfloat162_rn(a.x - __low2float(h01), a.y - __high2float(h01));
    __nv_bfloat162 l23 = __floats2bfloat162_rn(a.z - __low2float(h23), a.w - __high2float(h23));
    __nv_bfloat162 l45 = __floats2bfloat162_rn(b.x - __low2float(h45), b.y - __high2float(h45));
    __nv_bfloat162 l67 = __floats2bfloat162_rn(b.z - __low2float(h67), b.w - __high2float(h67));
    hi = make_uint4(b2u(h01), b2u(h23), b2u(h45), b2u(h67));
    lo = make_uint4(b2u(l01), b2u(l23), b2u(l45), b2u(l67));
}

// Split 4 fp32 into bf16 hi (uint2) and residual lo (uint2)
__device__ __forceinline__ void split4(float4 v, uint2& hi, uint2& lo) {
    __nv_bfloat162 h01 = __floats2bfloat162_rn(v.x, v.y);
    __nv_bfloat162 h23 = __floats2bfloat162_rn(v.z, v.w);
    __nv_bfloat162 l01 = __floats2bfloat162_rn(v.x - __low2float(h01), v.y - __high2float(h01));
    __nv_bfloat162 l23 = __floats2bfloat162_rn(v.z - __low2float(h23), v.w - __high2float(h23));
    hi = make_uint2(b2u(h01), b2u(h23));
    lo = make_uint2(b2u(l01), b2u(l23));
}

// ---------------------------------------------------------------------------
// Prep (merged): blocks 0-191 transpose+split QKV weights; 192-447 split Wo
// ---------------------------------------------------------------------------
__global__ void prep_all(const float* __restrict__ Wq, const float* __restrict__ Wk,
                         const float* __restrict__ Wv, const float* __restrict__ Wo) {
    int bid = blockIdx.x;
    if (bid < 192) {
        int n = bid;
        const float* W = (n < 64) ? Wq : ((n < 128) ? Wk : Wv);
        int col = n & 63;
        for (int k = threadIdx.x; k < H_; k += 256) {
            float w = W[(size_t)k * P_ + col];
            __nv_bfloat16 h = __float2bfloat16_rn(w);
            g_wt_hi[(size_t)n * H_ + k] = h;
            g_wt_lo[(size_t)n * H_ + k] = __float2bfloat16_rn(w - __bfloat162float(h));
        }
    } else {
        int idx = (bid - 192) * 256 + threadIdx.x;   // 0..65535
        int k = idx >> 10;
        int n = idx & 1023;
        float w = Wo[(size_t)k * H_ + n];
        __nv_bfloat16 h = __float2bfloat16_rn(w);
        g_wo_hi[(size_t)n * P_ + k] = h;
        g_wo_lo[(size_t)n * P_ + k] = __float2bfloat16_rn(w - __bfloat162float(h));
    }
}

// ---------------------------------------------------------------------------
// Kernel 1: fused QKV projection via mma.sync (unchanged from R11)
// ---------------------------------------------------------------------------
#define QKV_STAGE 51200
#define QKV_AH 0
#define QKV_AL 10240
#define QKV_BH 20480
#define QKV_BL 35840
#define QKV_SMEM (1024 + 2 * QKV_STAGE)   // 103424

__global__ __launch_bounds__(256) void qkv_mma(
    const float* __restrict__ X,
    const float* __restrict__ bq, const float* __restrict__ bk,
    const float* __restrict__ bv)
{
    extern __shared__ char smem[];
    const uint32_t sb = smem_u32(smem);
    const int tid = threadIdx.x, lane = tid & 31, wid = tid >> 5;
    const int wm = wid >> 2, wn = wid & 3;
    const int m0 = blockIdx.x * 128;

    float* bias_s = (float*)smem;
    if (tid < 192)
        bias_s[tid] = (tid < 64) ? bq[tid] : ((tid < 128) ? bk[tid - 64] : bv[tid - 128]);

    const int a_row = tid >> 1;
    const int a_seg = (tid & 1) * 16;
    const float* Xrow = X + (size_t)(m0 + a_row) * H_ + a_seg;

    const uint32_t a_off = (uint32_t)((wm * 64 + (lane & 15)) * 80 + (lane & 16));
    const uint32_t b_off = (uint32_t)((wn * 48 + (lane & 7) + ((lane & 16) >> 1)) * 80
                                      + ((lane & 8) << 1));

    float4 ar0, ar1, ar2, ar3;
    uint4 brh[3], brl[3];

    float acc[4][6][4];
#pragma unroll
    for (int i = 0; i < 4; i++)
#pragma unroll
        for (int j = 0; j < 6; j++)
#pragma unroll
            for (int c = 0; c < 4; c++) acc[i][j][c] = 0.f;

#define QKV_LDG(c) do {                                                          \
    int k0 = (c) * 32;                                                           \
    ar0 = *(const float4*)(Xrow + k0);                                           \
    ar1 = *(const float4*)(Xrow + k0 + 4);                                       \
    ar2 = *(const float4*)(Xrow + k0 + 8);                                       \
    ar3 = *(const float4*)(Xrow + k0 + 12);                                      \
    _Pragma("unroll")                                                            \
    for (int i = 0; i < 3; i++) {                                                \
        int idx = tid + i * 256; int n = idx >> 2, sg = idx & 3;                 \
        brh[i] = *(const uint4*)(g_wt_hi + (size_t)n * H_ + k0 + sg * 8);        \
        brl[i] = *(const uint4*)(g_wt_lo + (size_t)n * H_ + k0 + sg * 8);        \
    } } while (0)

#define QKV_STS(s) do {                                                          \
    char* bp = smem + 1024 + (s) * QKV_STAGE;                                    \
    uint4 hi0, lo0, hi1, lo1;                                                    \
    split8(ar0, ar1, hi0, lo0);                                                  \
    split8(ar2, ar3, hi1, lo1);                                                  \
    *(uint4*)(bp + QKV_AH + a_row * 80 + a_seg * 2)      = hi0;                  \
    *(uint4*)(bp + QKV_AH + a_row * 80 + a_seg * 2 + 16) = hi1;                  \
    *(uint4*)(bp + QKV_AL + a_row * 80 + a_seg * 2)      = lo0;                  \
    *(uint4*)(bp + QKV_AL + a_row * 80 + a_seg * 2 + 16) = lo1;                  \
    _Pragma("unroll")                                                            \
    for (int i = 0; i < 3; i++) {                                                \
        int idx = tid + i * 256; int n = idx >> 2, sg = idx & 3;                 \
        *(uint4*)(bp + QKV_BH + n * 80 + sg * 16) = brh[i];                      \
        *(uint4*)(bp + QKV_BL + n * 80 + sg * 16) = brl[i];                      \
    } } while (0)

    QKV_LDG(0);
    QKV_STS(0);
    __syncthreads();

    for (int c = 0; c < 32; ++c) {
        const int s = c & 1;
        if (c < 31) QKV_LDG(c + 1);
        const uint32_t base = sb + 1024 + s * QKV_STAGE;
#pragma unroll
        for (int ks = 0; ks < 2; ++ks) {
            uint32_t ah[4][4], al[4][4];
#pragma unroll
            for (int mt = 0; mt < 4; mt++) {
                ldsm4(ah[mt], base + QKV_AH + a_off + mt * 1280 + ks * 32);
                ldsm4(al[mt], base + QKV_AL + a_off + mt * 1280 + ks * 32);
            }
#pragma unroll
            for (int np = 0; np < 3; ++np) {
                uint32_t bh[4], bl[4];
                ldsm4(bh, base + QKV_BH + b_off + np * 1280 + ks * 32);
                ldsm4(bl, base + QKV_BL + b_off + np * 1280 + ks * 32);
#pragma unroll
                for (int hh = 0; hh < 2; ++hh) {
                    const int nt = np * 2 + hh;
#pragma unroll
                    for (int mt = 0; mt < 4; mt++) {
                        mma16816(acc[mt][nt], ah[mt], bh[2 * hh], bh[2 * hh + 1]);
                        mma16816(acc[mt][nt], ah[mt], bl[2 * hh], bl[2 * hh + 1]);
                        mma16816(acc[mt][nt], al[mt], bh[2 * hh], bh[2 * hh + 1]);
                    }
                }
            }
        }
        if (c < 31) { QKV_STS(s ^ 1); __syncthreads(); }
    }

    const int r0 = m0 + wm * 64 + (lane >> 2);
#pragma unroll
    for (int mt = 0; mt < 4; ++mt)
#pragma unroll
        for (int nt = 0; nt < 6; ++nt) {
            int n = wn * 48 + nt * 8 + (lane & 3) * 2;
            float* out = (n < 64) ? g_q : ((n < 128) ? g_k : g_v);
            int cn = n & 63;
            int row = r0 + mt * 16;
            float b0 = bias_s[n], b1 = bias_s[n + 1];
            *(float2*)(out + (size_t)row * P_ + cn) =
                make_float2(acc[mt][nt][0] + b0, acc[mt][nt][1] + b1);
            *(float2*)(out + (size_t)(row + 8) * P_ + cn) =
                make_float2(acc[mt][nt][2] + b0, acc[mt][nt][3] + b1);
        }
}

// ---------------------------------------------------------------------------
// Kernel 2: banded attention via mma.sync — smem lifetime overlap version.
// K region (55.3KB) is reused for transposed V (51.2KB, staged AFTER S);
// Q region (18.4KB) is reused for PART (16.9KB).  Total 75.5KB -> 2 CTA/SM,
// 256 blocks fit one wave (296 slots).
// ---------------------------------------------------------------------------
#define AT_KH   0
#define AT_KL   27648
#define AT_VH   0
#define AT_VL   25600
#define AT_QH   55296
#define AT_QL   64512
#define AT_PART 55296
#define AT_BIAS 73728
#define AT_MAX  74496
#define AT_SUM  75008
#define AT_SMEM 75520

__global__ __launch_bounds__(256, 2) void attn_mma(const float* __restrict__ biasg)
{
    extern __shared__ char smem[];
    const uint32_t sb = smem_u32(smem);
    const int tid = threadIdx.x, lane = tid & 31, w = tid >> 5;
    const int h = w >> 2, rb = w & 3;
    const int b  = blockIdx.x >> 5;
    const int t0 = (blockIdx.x & 31) << 6;

    const float* Kg = g_k + (size_t)b * T_ * P_;
    const float* Vg = g_v + (size_t)b * T_ * P_;
    const float* Qg = g_q + ((size_t)b * T_ + t0) * P_;

    // ---- Stage K band ([192][72] bf16 hi/lo) — V staged later into this space
    for (int idx = tid; idx < 192 * 16; idx += 256) {
        int j = idx >> 4, d4 = (idx & 15) << 2;
        int jg = t0 - 64 + j;
        float4 kv = make_float4(0.f, 0.f, 0.f, 0.f);
        if (jg >= 0 && jg < T_)
            kv = *(const float4*)(Kg + (size_t)jg * P_ + d4);
        uint2 khi, klo;
        split4(kv, khi, klo);
        *(uint2*)(smem + AT_KH + j * 144 + d4 * 2) = khi;
        *(uint2*)(smem + AT_KL + j * 144 + d4 * 2) = klo;
    }
    // ---- Stage Q ([64][72] bf16 hi/lo)
    for (int idx = tid; idx < 64 * 16; idx += 256) {
        int r = idx >> 4, d4 = (idx & 15) << 2;
        float4 qv = *(const float4*)(Qg + (size_t)r * P_ + d4);
        uint2 qhi, qlo;
        split4(qv, qhi, qlo);
        *(uint2*)(smem + AT_QH + r * 144 + d4 * 2) = qhi;
        *(uint2*)(smem + AT_QL + r * 144 + d4 * 2) = qlo;
    }
    float* bias_s = (float*)(smem + AT_BIAS);
    for (int d = tid; d < 192; d += 256)
        bias_s[d] = (d <= 128) ? biasg[1984 + d] : 0.f;
    __syncthreads();

    // ---- S = Q @ K^T
    const uint32_t a_off = (uint32_t)((rb * 16 + (lane & 15)) * 144 + (lane & 16));
    const uint32_t b_off = (uint32_t)(((lane & 7) + ((lane & 16) >> 1)) * 144
                                      + ((lane & 8) << 1));
    float acc[12][4];
#pragma unroll
    for (int nt = 0; nt < 12; nt++)
#pragma unroll
        for (int c = 0; c < 4; c++) acc[nt][c] = 0.f;

#pragma unroll
    for (int ks = 0; ks < 4; ++ks) {
        uint32_t qh[4], ql[4];
        ldsm4(qh, sb + AT_QH + a_off + ks * 32);
        ldsm4(ql, sb + AT_QL + a_off + ks * 32);
#pragma unroll
        for (int np = 0; np < 6; ++np) {
            uint32_t kb = sb + b_off + (uint32_t)((h * 96 + np * 16) * 144) + ks * 32;
            uint32_t kh4[4], kl4[4];
            ldsm4(kh4, kb + AT_KH);
            ldsm4(kl4, kb + AT_KL);
#pragma unroll
            for (int hh = 0; hh < 2; ++hh) {
                const int nt = np * 2 + hh;
                mma16816(acc[nt], qh, kh4[2 * hh], kh4[2 * hh + 1]);
                mma16816(acc[nt], qh, kl4[2 * hh], kl4[2 * hh + 1]);
                mma16816(acc[nt], ql, kh4[2 * hh], kh4[2 * hh + 1]);
            }
        }
    }

    // ---- mask + bias + softmax
    const int r1 = rb * 16 + (lane >> 2);
    const int r2 = r1 + 8;
    float* smax = (float*)(smem + AT_MAX);
    float* ssum = (float*)(smem + AT_SUM);

    float m1 = -1e30f, m2v = -1e30f;
#pragma unroll
    for (int nt = 0; nt < 12; nt++) {
        int cbase = h * 96 + nt * 8 + 2 * (lane & 3);
#pragma unroll
        for (int e = 0; e < 2; e++) {
            int c = cbase + e;
            int jg = t0 - 64 + c;
            bool jv = (jg >= 0 && jg < T_);
            int rel1 = c - r1;
            bool v1 = jv && rel1 >= 0 && rel1 <= 128;
            float s1v = v1 ? fmaf(acc[nt][e], 0.125f, bias_s[rel1]) : -1e30f;
            acc[nt][e] = s1v;
            m1 = fmaxf(m1, s1v);
            int rel2 = c - r2;
            bool v2 = jv && rel2 >= 0 && rel2 <= 128;
            float s2v = v2 ? fmaf(acc[nt][2 + e], 0.125f, bias_s[rel2]) : -1e30f;
            acc[nt][2 + e] = s2v;
            m2v = fmaxf(m2v, s2v);
        }
    }
    m1  = fmaxf(m1,  __shfl_xor_sync(0xffffffffu, m1, 1));
    m1  = fmaxf(m1,  __shfl_xor_sync(0xffffffffu, m1, 2));
    m2v = fmaxf(m2v, __shfl_xor_sync(0xffffffffu, m2v, 1));
    m2v = fmaxf(m2v, __shfl_xor_sync(0xffffffffu, m2v, 2));
    if ((lane & 3) == 0) {
        smax[h * 64 + r1] = m1;
        smax[h * 64 + r2] = m2v;
    }
    __syncthreads();   // also: all S-phase ldsm of K complete after this point
    const float gm1 = fmaxf(smax[r1], smax[64 + r1]);
    const float gm2 = fmaxf(smax[r2], smax[64 + r2]);

    float su1 = 0.f, su2 = 0.f;
#pragma unroll
    for (int nt = 0; nt < 12; nt++) {
#pragma unroll
        for (int e = 0; e < 2; e++) {
            float p1 = __expf(acc[nt][e] - gm1);
            float p2 = __expf(acc[nt][2 + e] - gm2);
            acc[nt][e] = p1;
            acc[nt][2 + e] = p2;
            su1 += p1;
            su2 += p2;
        }
    }
    su1 += __shfl_xor_sync(0xffffffffu, su1, 1);
    su1 += __shfl_xor_sync(0xffffffffu, su1, 2);
    su2 += __shfl_xor_sync(0xffffffffu, su2, 1);
    su2 += __shfl_xor_sync(0xffffffffu, su2, 2);
    if ((lane & 3) == 0) {
        ssum[h * 64 + r1] = su1;
        ssum[h * 64 + r2] = su2;
    }

    // ---- Stage transposed V into the retired K region ([64][200] hi/lo)
    for (int idx = tid; idx < 192 * 16; idx += 256) {
        int j = idx >> 4, d4 = (idx & 15) << 2;
        int jg = t0 - 64 + j;
        float4 vv = make_float4(0.f, 0.f, 0.f, 0.f);
        if (jg >= 0 && jg < T_)
            vv = *(const float4*)(Vg + (size_t)jg * P_ + d4);
        float vals[4] = {vv.x, vv.y, vv.z, vv.w};
#pragma unroll
        for (int i = 0; i < 4; i++) {
            int d = d4 + i;
            __nv_bfloat16 vh = __float2bfloat16_rn(vals[i]);
            *(__nv_bfloat16*)(smem + AT_VH + d * 400 + j * 2) = vh;
            *(__nv_bfloat16*)(smem + AT_VL + d * 400 + j * 2) =
                __float2bfloat16_rn(vals[i] - __bfloat162float(vh));
        }
    }

    // ---- P -> A fragments (reg-to-reg), split hi/lo
    uint32_t ph[24], pl[24];
#pragma unroll
    for (int nt = 0; nt < 12; nt++) {
        __nv_bfloat162 h01 = __floats2bfloat162_rn(acc[nt][0], acc[nt][1]);
        __nv_bfloat162 h23 = __floats2bfloat162_rn(acc[nt][2], acc[nt][3]);
        ph[2 * nt]     = b2u(h01);
        ph[2 * nt + 1] = b2u(h23);
        pl[2 * nt]     = b2u(__floats2bfloat162_rn(acc[nt][0] - __low2float(h01),
                                                   acc[nt][1] - __high2float(h01)));
        pl[2 * nt + 1] = b2u(__floats2bfloat162_rn(acc[nt][2] - __low2float(h23),
                                                   acc[nt][3] - __high2float(h23)));
    }
    __syncthreads();   // V staged + ssum visible

    // ---- O_partial = P @ V over this warp's 96 keys
    const uint32_t vt_off = (uint32_t)(((lane & 7) + ((lane & 16) >> 1)) * 400
                                       + ((lane & 8) << 1) + h * 192);
    float oacc[8][4];
#pragma unroll
    for (int nt = 0; nt < 8; nt++)
#pragma unroll
        for (int c = 0; c < 4; c++) oacc[nt][c] = 0.f;

#pragma unroll
    for (int kk = 0; kk < 6; ++kk) {
        const uint32_t* aph = ph + kk * 4;
        const uint32_t* apl = pl + kk * 4;
#pragma unroll
        for (int nv = 0; nv < 4; ++nv) {
            uint32_t vb = sb + vt_off + (uint32_t)(nv * 6400) + kk * 32;
            uint32_t vh4[4], vl4[4];
            ldsm4(vh4, vb + AT_VH);
            ldsm4(vl4, vb + AT_VL);
#pragma unroll
            for (int hh = 0; hh < 2; ++hh) {
                const int nt = nv * 2 + hh;
                mma16816(oacc[nt], aph, vh4[2 * hh], vh4[2 * hh + 1]);
                mma16816(oacc[nt], aph, vl4[2 * hh], vl4[2 * hh + 1]);
                mma16816(oacc[nt], apl, vh4[2 * hh], vh4[2 * hh + 1]);
            }
        }
    }

    // ---- combine halves via PART (overlaid on retired Q region)
    float* part = (float*)(smem + AT_PART);   // [64][66] fp32
    if (h == 1) {
#pragma unroll
        for (int nt = 0; nt < 8; nt++) {
            int col = nt * 8 + 2 * (lane & 3);
            *(float2*)(part + r1 * 66 + col) = make_float2(oacc[nt][0], oacc[nt][1]);
            *(float2*)(part + r2 * 66 + col) = make_float2(oacc[nt][2], oacc[nt][3]);
        }
    }
    __syncthreads();
    if (h == 0) {
        const float inv1 = 1.f / (ssum[r1] + ssum[64 + r1]);
        const float inv2 = 1.f / (ssum[r2] + ssum[64 + r2]);
        float* O1 = g_att + ((size_t)b * T_ + t0 + r1) * P_;
        float* O2 = g_att + ((size_t)b * T_ + t0 + r2) * P_;
#pragma unroll
        for (int nt = 0; nt < 8; nt++) {
            int col = nt * 8 + 2 * (lane & 3);
            float2 p1 = *(float2*)(part + r1 * 66 + col);
            float2 p2 = *(float2*)(part + r2 * 66 + col);
            *(float2*)(O1 + col) = make_float2((oacc[nt][0] + p1.x) * inv1,
                                               (oacc[nt][1] + p1.y) * inv1);
            *(float2*)(O2 + col) = make_float2((oacc[nt][2] + p2.x) * inv2,
                                               (oacc[nt][3] + p2.y) * inv2);
        }
    }
}

// ---------------------------------------------------------------------------
// Kernel 3: output projection, persistent m-block (unchanged from R11)
// ---------------------------------------------------------------------------
#define OP2_AH 0
#define OP2_AL 9216
#define OP2_B  18432
#define OP2_BSTAGE 36864
#define OP2_SMEM (18432 + 2 * 36864)   // 92160

__global__ __launch_bounds__(256) void outproj_mma(
    const float* __restrict__ bo, float* __restrict__ O)
{
    extern __shared__ char smem[];
    const uint32_t sb = smem_u32(smem);
    const int tid = threadIdx.x, lane = tid & 31, wid = tid >> 5;
    const int wm = wid >> 2, wn = wid & 3;
    const int m0 = blockIdx.x * 64;

    {
        int row = tid >> 2, ks = (tid & 3) * 16;
        const float* ap = g_att + (size_t)(m0 + row) * P_ + ks;
        float4 f0 = *(const float4*)(ap + 0);
        float4 f1 = *(const float4*)(ap + 4);
        float4 f2 = *(const float4*)(ap + 8);
        float4 f3 = *(const float4*)(ap + 12);
        uint4 hi0, lo0, hi1, lo1;
        split8(f0, f1, hi0, lo0);
        split8(f2, f3, hi1, lo1);
        *(uint4*)(smem + OP2_AH + row * 144 + ks * 2)      = hi0;
        *(uint4*)(smem + OP2_AH + row * 144 + ks * 2 + 16) = hi1;
        *(uint4*)(smem + OP2_AL + row * 144 + ks * 2)      = lo0;
        *(uint4*)(smem + OP2_AL + row * 144 + ks * 2 + 16) = lo1;
    }

    uint4 brh[4], brl[4];
#define OP_LDG(nb) do {                                                          \
    int n0 = (nb) * 128;                                                         \
    _Pragma("unroll")                                                            \
    for (int i = 0; i < 4; i++) {                                                \
        int idx = tid + i * 256; int n = idx >> 3, sg = idx & 7;                 \
        brh[i] = *(const uint4*)(g_wo_hi + (size_t)(n0 + n) * P_ + sg * 8);      \
        brl[i] = *(const uint4*)(g_wo_lo + (size_t)(n0 + n) * P_ + sg * 8);      \
    } } while (0)

#define OP_STS(s) do {                                                           \
    char* bp = smem + OP2_B + (s) * OP2_BSTAGE;                                  \
    _Pragma("unroll")                                                            \
    for (int i = 0; i < 4; i++) {                                                \
        int idx = tid + i * 256; int n = idx >> 3, sg = idx & 7;                 \
        *(uint4*)(bp + n * 144 + sg * 16)         = brh[i];                      \
        *(uint4*)(bp + 18432 + n * 144 + sg * 16) = brl[i];                      \
    } } while (0)

    OP_LDG(0);
    __syncthreads();

    const uint32_t a_off = (uint32_t)((wm * 32 + (lane & 15)) * 144 + (lane & 16));
    uint32_t ahf[4][2][4], alf[4][2][4];
#pragma unroll
    for (int ks = 0; ks < 4; ++ks)
#pragma unroll
        for (int mt = 0; mt < 2; ++mt) {
            ldsm4(ahf[ks][mt], sb + OP2_AH + a_off + mt * 2304 + ks * 32);
            ldsm4(alf[ks][mt], sb + OP2_AL + a_off + mt * 2304 + ks * 32);
        }

    OP_STS(0);
    __syncthreads();

    const uint32_t b_off = (uint32_t)((wn * 32 + (lane & 7) + ((lane & 16) >> 1)) * 144
                                      + ((lane & 8) << 1));
    const int r0 = m0 + wm * 32 + (lane >> 2);

    for (int nb = 0; nb < 8; ++nb) {
        const int s = nb & 1;
        if (nb < 7) OP_LDG(nb + 1);

        float acc[2][4][4];
#pragma unroll
        for (int i = 0; i < 2; i++)
#pragma unroll
            for (int j = 0; j < 4; j++)
#pragma unroll
                for (int c = 0; c < 4; c++) acc[i][j][c] = 0.f;

        const uint32_t bbase = sb + OP2_B + s * OP2_BSTAGE;
#pragma unroll
        for (int ks = 0; ks < 4; ++ks) {
#pragma unroll
            for (int np = 0; np < 2; ++np) {
                uint32_t bh[4], bl[4];
                ldsm4(bh, bbase + b_off + np * 2304 + ks * 32);
                ldsm4(bl, bbase + 18432 + b_off + np * 2304 + ks * 32);
#pragma unroll
                for (int hh = 0; hh < 2; ++hh) {
                    const int nt = np * 2 + hh;
#pragma unroll
                    for (int mt = 0; mt < 2; ++mt) {
                        mma16816(acc[mt][nt], ahf[ks][mt], bh[2 * hh], bh[2 * hh + 1]);
                        mma16816(acc[mt][nt], ahf[ks][mt], bl[2 * hh], bl[2 * hh + 1]);
                        mma16816(acc[mt][nt], alf[ks][mt], bh[2 * hh], bh[2 * hh + 1]);
                    }
                }
            }
        }

        const int n0 = nb * 128;
#pragma unroll
        for (int mt = 0; mt < 2; ++mt)
#pragma unroll
            for (int nt = 0; nt < 4; ++nt) {
                int n = n0 + wn * 32 + nt * 8 + (lane & 3) * 2;
                int row = r0 + mt * 16;
                float b0 = __ldg(bo + n), b1 = __ldg(bo + n + 1);
                *(float2*)(O + (size_t)row * H_ + n) =
                    make_float2(acc[mt][nt][0] + b0, acc[mt][nt][1] + b1);
                *(float2*)(O + (size_t)(row + 8) * H_ + n) =
                    make_float2(acc[mt][nt][2] + b0, acc[mt][nt][3] + b1);
            }

        if (nb < 7) { OP_STS(s ^ 1); __syncthreads(); }
    }
}

// ---------------------------------------------------------------------------
// Launch
// ---------------------------------------------------------------------------
extern "C" void kernel_launch(void* const* d_in, const int* in_sizes, int n_in,
                              void* d_out, int out_size)
{
    (void)in_sizes; (void)n_in; (void)out_size;
    const float* X    = (const float*)d_in[0];
    const float* Wq   = (const float*)d_in[2];
    const float* bq   = (const float*)d_in[3];
    const float* Wk   = (const float*)d_in[4];
    const float* bk   = (const float*)d_in[5];
    const float* Wv   = (const float*)d_in[6];
    const float* bv   = (const float*)d_in[7];
    const float* Wo   = (const float*)d_in[8];
    const float* bo   = (const float*)d_in[9];
    const float* bias = (const float*)d_in[10];
    float* O = (float*)d_out;

    prep_all<<<448, 256>>>(Wq, Wk, Wv, Wo);

    cudaFuncSetAttribute(qkv_mma, cudaFuncAttributeMaxDynamicSharedMemorySize,
                         QKV_SMEM);
    qkv_mma<<<128, 256, QKV_SMEM>>>(X, bq, bk, bv);

    cudaFuncSetAttribute(attn_mma, cudaFuncAttributeMaxDynamicSharedMemorySize,
                         AT_SMEM);
    attn_mma<<<256, 256, AT_SMEM>>>(bias);

    cudaFuncSetAttribute(outproj_mma, cudaFuncAttributeMaxDynamicSharedMemorySize,
                         OP2_SMEM);
    outproj_mma<<<256, 256, OP2_SMEM>>>(bo, O);
}

// round 14
// speedup vs baseline: 2.7436x; 1.0142x over previous
#include <cuda_runtime.h>
#include <cuda_bf16.h>
#include <cstdint>

#define B_ 8
#define T_ 2048
#define H_ 1024
#define P_ 64
#define BT_ (B_ * T_)

// Scratch (no cudaMalloc allowed)
__device__ float g_q[BT_ * P_];
__device__ float g_k[BT_ * P_];
__device__ float g_v[BT_ * P_];
__device__ float g_att[BT_ * P_];
// QKV weights transposed to [n][k] (n=192, k=1024), split bf16 hi/lo
__device__ __align__(16) __nv_bfloat16 g_wt_hi[192 * 1024];
__device__ __align__(16) __nv_bfloat16 g_wt_lo[192 * 1024];
// Wo transposed to [n][k] (n=1024, k=64), split bf16 hi/lo
__device__ __align__(16) __nv_bfloat16 g_wo_hi[1024 * 64];
__device__ __align__(16) __nv_bfloat16 g_wo_lo[1024 * 64];

// ---------------------------------------------------------------------------
// Base-ISA tensor helpers (sm_80+; compile at plain sm_103)
// ---------------------------------------------------------------------------
__device__ __forceinline__ uint32_t smem_u32(const void* p) {
    uint32_t a;
    asm("{ .reg .u64 t; cvta.to.shared.u64 t, %1; cvt.u32.u64 %0, t; }"
        : "=r"(a) : "l"(p));
    return a;
}

__device__ __forceinline__ void ldsm4(uint32_t* r, uint32_t addr) {
    asm volatile("ldmatrix.sync.aligned.m8n8.x4.shared.b16 {%0,%1,%2,%3}, [%4];"
                 : "=r"(r[0]), "=r"(r[1]), "=r"(r[2]), "=r"(r[3]) : "r"(addr));
}

__device__ __forceinline__ void mma16816(float* d, const uint32_t* a,
                                         uint32_t b0, uint32_t b1) {
    asm volatile(
        "mma.sync.aligned.m16n8k16.row.col.f32.bf16.bf16.f32 "
        "{%0,%1,%2,%3}, {%4,%5,%6,%7}, {%8,%9}, {%0,%1,%2,%3};"
        : "+f"(d[0]), "+f"(d[1]), "+f"(d[2]), "+f"(d[3])
        : "r"(a[0]), "r"(a[1]), "r"(a[2]), "r"(a[3]), "r"(b0), "r"(b1));
}

__device__ __forceinline__ uint32_t b2u(__nv_bfloat162 v) {
    union { __nv_bfloat162 b; uint32_t u; } c;
    c.b = v;
    return c.u;
}

// Split 8 fp32 into bf16 hi (uint4) and residual lo (uint4)
__device__ __forceinline__ void split8(float4 a, float4 b, uint4& hi, uint4& lo) {
    __nv_bfloat162 h01 = __floats2bfloat162_rn(a.x, a.y);
    __nv_bfloat162 h23 = __floats2bfloat162_rn(a.z, a.w);
    __nv_bfloat162 h45 = __floats2bfloat162_rn(b.x, b.y);
    __nv_bfloat162 h67 = __floats2bfloat162_rn(b.z, b.w);
    __nv_bfloat162 l01 = __floats2bfloat162_rn(a.x - __low2float(h01), a.y - __high2float(h01));
    __nv_bfloat162 l23 = __floats2bfloat162_rn(a.z - __low2float(h23), a.w - __high2float(h23));
    __nv_bfloat162 l45 = __floats2bfloat162_rn(b.x - __low2float(h45), b.y - __high2float(h45));
    __nv_bfloat162 l67 = __floats2bfloat162_rn(b.z - __low2float(h67), b.w - __high2float(h67));
    hi = make_uint4(b2u(h01), b2u(h23), b2u(h45), b2u(h67));
    lo = make_uint4(b2u(l01), b2u(l23), b2u(l45), b2u(l67));
}

// Split 4 fp32 into bf16 hi (uint2) and residual lo (uint2)
__device__ __forceinline__ void split4(float4 v, uint2& hi, uint2& lo) {
    __nv_bfloat162 h01 = __floats2bfloat162_rn(v.x, v.y);
    __nv_bfloat162 h23 = __floats2bfloat162_rn(v.z, v.w);
    __nv_bfloat162 l01 = __floats2bfloat162_rn(v.x - __low2float(h01), v.y - __high2float(h01));
    __nv_bfloat162 l23 = __floats2bfloat162_rn(v.z - __low2float(h23), v.w - __high2float(h23));
    hi = make_uint2(b2u(h01), b2u(h23));
    lo = make_uint2(b2u(l01), b2u(l23));
}

// ---------------------------------------------------------------------------
// Prep (merged): blocks 0-191 transpose+split QKV weights; 192-447 split Wo
// ---------------------------------------------------------------------------
__global__ void prep_all(const float* __restrict__ Wq, const float* __restrict__ Wk,
                         const float* __restrict__ Wv, const float* __restrict__ Wo) {
    int bid = blockIdx.x;
    if (bid < 192) {
        int n = bid;
        const float* W = (n < 64) ? Wq : ((n < 128) ? Wk : Wv);
        int col = n & 63;
        for (int k = threadIdx.x; k < H_; k += 256) {
            float w = W[(size_t)k * P_ + col];
            __nv_bfloat16 h = __float2bfloat16_rn(w);
            g_wt_hi[(size_t)n * H_ + k] = h;
            g_wt_lo[(size_t)n * H_ + k] = __float2bfloat16_rn(w - __bfloat162float(h));
        }
    } else {
        int idx = (bid - 192) * 256 + threadIdx.x;   // 0..65535
        int k = idx >> 10;
        int n = idx & 1023;
        float w = Wo[(size_t)k * H_ + n];
        __nv_bfloat16 h = __float2bfloat16_rn(w);
        g_wo_hi[(size_t)n * P_ + k] = h;
        g_wo_lo[(size_t)n * P_ + k] = __float2bfloat16_rn(w - __bfloat162float(h));
    }
}

// ---------------------------------------------------------------------------
// Kernel 1: fused QKV projection via mma.sync (unchanged from R11)
// ---------------------------------------------------------------------------
#define QKV_STAGE 51200
#define QKV_AH 0
#define QKV_AL 10240
#define QKV_BH 20480
#define QKV_BL 35840
#define QKV_SMEM (1024 + 2 * QKV_STAGE)   // 103424

__global__ __launch_bounds__(256) void qkv_mma(
    const float* __restrict__ X,
    const float* __restrict__ bq, const float* __restrict__ bk,
    const float* __restrict__ bv)
{
    extern __shared__ char smem[];
    const uint32_t sb = smem_u32(smem);
    const int tid = threadIdx.x, lane = tid & 31, wid = tid >> 5;
    const int wm = wid >> 2, wn = wid & 3;
    const int m0 = blockIdx.x * 128;

    float* bias_s = (float*)smem;
    if (tid < 192)
        bias_s[tid] = (tid < 64) ? bq[tid] : ((tid < 128) ? bk[tid - 64] : bv[tid - 128]);

    const int a_row = tid >> 1;
    const int a_seg = (tid & 1) * 16;
    const float* Xrow = X + (size_t)(m0 + a_row) * H_ + a_seg;

    const uint32_t a_off = (uint32_t)((wm * 64 + (lane & 15)) * 80 + (lane & 16));
    const uint32_t b_off = (uint32_t)((wn * 48 + (lane & 7) + ((lane & 16) >> 1)) * 80
                                      + ((lane & 8) << 1));

    float4 ar0, ar1, ar2, ar3;
    uint4 brh[3], brl[3];

    float acc[4][6][4];
#pragma unroll
    for (int i = 0; i < 4; i++)
#pragma unroll
        for (int j = 0; j < 6; j++)
#pragma unroll
            for (int c = 0; c < 4; c++) acc[i][j][c] = 0.f;

#define QKV_LDG(c) do {                                                          \
    int k0 = (c) * 32;                                                           \
    ar0 = *(const float4*)(Xrow + k0);                                           \
    ar1 = *(const float4*)(Xrow + k0 + 4);                                       \
    ar2 = *(const float4*)(Xrow + k0 + 8);                                       \
    ar3 = *(const float4*)(Xrow + k0 + 12);                                      \
    _Pragma("unroll")                                                            \
    for (int i = 0; i < 3; i++) {                                                \
        int idx = tid + i * 256; int n = idx >> 2, sg = idx & 3;                 \
        brh[i] = *(const uint4*)(g_wt_hi + (size_t)n * H_ + k0 + sg * 8);        \
        brl[i] = *(const uint4*)(g_wt_lo + (size_t)n * H_ + k0 + sg * 8);        \
    } } while (0)

#define QKV_STS(s) do {                                                          \
    char* bp = smem + 1024 + (s) * QKV_STAGE;                                    \
    uint4 hi0, lo0, hi1, lo1;                                                    \
    split8(ar0, ar1, hi0, lo0);                                                  \
    split8(ar2, ar3, hi1, lo1);                                                  \
    *(uint4*)(bp + QKV_AH + a_row * 80 + a_seg * 2)      = hi0;                  \
    *(uint4*)(bp + QKV_AH + a_row * 80 + a_seg * 2 + 16) = hi1;                  \
    *(uint4*)(bp + QKV_AL + a_row * 80 + a_seg * 2)      = lo0;                  \
    *(uint4*)(bp + QKV_AL + a_row * 80 + a_seg * 2 + 16) = lo1;                  \
    _Pragma("unroll")                                                            \
    for (int i = 0; i < 3; i++) {                                                \
        int idx = tid + i * 256; int n = idx >> 2, sg = idx & 3;                 \
        *(uint4*)(bp + QKV_BH + n * 80 + sg * 16) = brh[i];                      \
        *(uint4*)(bp + QKV_BL + n * 80 + sg * 16) = brl[i];                      \
    } } while (0)

    QKV_LDG(0);
    QKV_STS(0);
    __syncthreads();

    for (int c = 0; c < 32; ++c) {
        const int s = c & 1;
        if (c < 31) QKV_LDG(c + 1);
        const uint32_t base = sb + 1024 + s * QKV_STAGE;
#pragma unroll
        for (int ks = 0; ks < 2; ++ks) {
            uint32_t ah[4][4], al[4][4];
#pragma unroll
            for (int mt = 0; mt < 4; mt++) {
                ldsm4(ah[mt], base + QKV_AH + a_off + mt * 1280 + ks * 32);
                ldsm4(al[mt], base + QKV_AL + a_off + mt * 1280 + ks * 32);
            }
#pragma unroll
            for (int np = 0; np < 3; ++np) {
                uint32_t bh[4], bl[4];
                ldsm4(bh, base + QKV_BH + b_off + np * 1280 + ks * 32);
                ldsm4(bl, base + QKV_BL + b_off + np * 1280 + ks * 32);
#pragma unroll
                for (int hh = 0; hh < 2; ++hh) {
                    const int nt = np * 2 + hh;
#pragma unroll
                    for (int mt = 0; mt < 4; mt++) {
                        mma16816(acc[mt][nt], ah[mt], bh[2 * hh], bh[2 * hh + 1]);
                        mma16816(acc[mt][nt], ah[mt], bl[2 * hh], bl[2 * hh + 1]);
                        mma16816(acc[mt][nt], al[mt], bh[2 * hh], bh[2 * hh + 1]);
                    }
                }
            }
        }
        if (c < 31) { QKV_STS(s ^ 1); __syncthreads(); }
    }

    const int r0 = m0 + wm * 64 + (lane >> 2);
#pragma unroll
    for (int mt = 0; mt < 4; ++mt)
#pragma unroll
        for (int nt = 0; nt < 6; ++nt) {
            int n = wn * 48 + nt * 8 + (lane & 3) * 2;
            float* out = (n < 64) ? g_q : ((n < 128) ? g_k : g_v);
            int cn = n & 63;
            int row = r0 + mt * 16;
            float b0 = bias_s[n], b1 = bias_s[n + 1];
            *(float2*)(out + (size_t)row * P_ + cn) =
                make_float2(acc[mt][nt][0] + b0, acc[mt][nt][1] + b1);
            *(float2*)(out + (size_t)(row + 8) * P_ + cn) =
                make_float2(acc[mt][nt][2] + b0, acc[mt][nt][3] + b1);
        }
}

// ---------------------------------------------------------------------------
// Kernel 2: banded attention via mma.sync — smem lifetime overlap (R13, 2 CTA/SM)
// ---------------------------------------------------------------------------
#define AT_KH   0
#define AT_KL   27648
#define AT_VH   0
#define AT_VL   25600
#define AT_QH   55296
#define AT_QL   64512
#define AT_PART 55296
#define AT_BIAS 73728
#define AT_MAX  74496
#define AT_SUM  75008
#define AT_SMEM 75520

__global__ __launch_bounds__(256, 2) void attn_mma(const float* __restrict__ biasg)
{
    extern __shared__ char smem[];
    const uint32_t sb = smem_u32(smem);
    const int tid = threadIdx.x, lane = tid & 31, w = tid >> 5;
    const int h = w >> 2, rb = w & 3;
    const int b  = blockIdx.x >> 5;
    const int t0 = (blockIdx.x & 31) << 6;

    const float* Kg = g_k + (size_t)b * T_ * P_;
    const float* Vg = g_v + (size_t)b * T_ * P_;
    const float* Qg = g_q + ((size_t)b * T_ + t0) * P_;

    for (int idx = tid; idx < 192 * 16; idx += 256) {
        int j = idx >> 4, d4 = (idx & 15) << 2;
        int jg = t0 - 64 + j;
        float4 kv = make_float4(0.f, 0.f, 0.f, 0.f);
        if (jg >= 0 && jg < T_)
            kv = *(const float4*)(Kg + (size_t)jg * P_ + d4);
        uint2 khi, klo;
        split4(kv, khi, klo);
        *(uint2*)(smem + AT_KH + j * 144 + d4 * 2) = khi;
        *(uint2*)(smem + AT_KL + j * 144 + d4 * 2) = klo;
    }
    for (int idx = tid; idx < 64 * 16; idx += 256) {
        int r = idx >> 4, d4 = (idx & 15) << 2;
        float4 qv = *(const float4*)(Qg + (size_t)r * P_ + d4);
        uint2 qhi, qlo;
        split4(qv, qhi, qlo);
        *(uint2*)(smem + AT_QH + r * 144 + d4 * 2) = qhi;
        *(uint2*)(smem + AT_QL + r * 144 + d4 * 2) = qlo;
    }
    float* bias_s = (float*)(smem + AT_BIAS);
    for (int d = tid; d < 192; d += 256)
        bias_s[d] = (d <= 128) ? biasg[1984 + d] : 0.f;
    __syncthreads();

    const uint32_t a_off = (uint32_t)((rb * 16 + (lane & 15)) * 144 + (lane & 16));
    const uint32_t b_off = (uint32_t)(((lane & 7) + ((lane & 16) >> 1)) * 144
                                      + ((lane & 8) << 1));
    float acc[12][4];
#pragma unroll
    for (int nt = 0; nt < 12; nt++)
#pragma unroll
        for (int c = 0; c < 4; c++) acc[nt][c] = 0.f;

#pragma unroll
    for (int ks = 0; ks < 4; ++ks) {
        uint32_t qh[4], ql[4];
        ldsm4(qh, sb + AT_QH + a_off + ks * 32);
        ldsm4(ql, sb + AT_QL + a_off + ks * 32);
#pragma unroll
        for (int np = 0; np < 6; ++np) {
            uint32_t kb = sb + b_off + (uint32_t)((h * 96 + np * 16) * 144) + ks * 32;
            uint32_t kh4[4], kl4[4];
            ldsm4(kh4, kb + AT_KH);
            ldsm4(kl4, kb + AT_KL);
#pragma unroll
            for (int hh = 0; hh < 2; ++hh) {
                const int nt = np * 2 + hh;
                mma16816(acc[nt], qh, kh4[2 * hh], kh4[2 * hh + 1]);
                mma16816(acc[nt], qh, kl4[2 * hh], kl4[2 * hh + 1]);
                mma16816(acc[nt], ql, kh4[2 * hh], kh4[2 * hh + 1]);
            }
        }
    }

    const int r1 = rb * 16 + (lane >> 2);
    const int r2 = r1 + 8;
    float* smax = (float*)(smem + AT_MAX);
    float* ssum = (float*)(smem + AT_SUM);

    float m1 = -1e30f, m2v = -1e30f;
#pragma unroll
    for (int nt = 0; nt < 12; nt++) {
        int cbase = h * 96 + nt * 8 + 2 * (lane & 3);
#pragma unroll
        for (int e = 0; e < 2; e++) {
            int c = cbase + e;
            int jg = t0 - 64 + c;
            bool jv = (jg >= 0 && jg < T_);
            int rel1 = c - r1;
            bool v1 = jv && rel1 >= 0 && rel1 <= 128;
            float s1v = v1 ? fmaf(acc[nt][e], 0.125f, bias_s[rel1]) : -1e30f;
            acc[nt][e] = s1v;
            m1 = fmaxf(m1, s1v);
            int rel2 = c - r2;
            bool v2 = jv && rel2 >= 0 && rel2 <= 128;
            float s2v = v2 ? fmaf(acc[nt][2 + e], 0.125f, bias_s[rel2]) : -1e30f;
            acc[nt][2 + e] = s2v;
            m2v = fmaxf(m2v, s2v);
        }
    }
    m1  = fmaxf(m1,  __shfl_xor_sync(0xffffffffu, m1, 1));
    m1  = fmaxf(m1,  __shfl_xor_sync(0xffffffffu, m1, 2));
    m2v = fmaxf(m2v, __shfl_xor_sync(0xffffffffu, m2v, 1));
    m2v = fmaxf(m2v, __shfl_xor_sync(0xffffffffu, m2v, 2));
    if ((lane & 3) == 0) {
        smax[h * 64 + r1] = m1;
        smax[h * 64 + r2] = m2v;
    }
    __syncthreads();
    const float gm1 = fmaxf(smax[r1], smax[64 + r1]);
    const float gm2 = fmaxf(smax[r2], smax[64 + r2]);

    float su1 = 0.f, su2 = 0.f;
#pragma unroll
    for (int nt = 0; nt < 12; nt++) {
#pragma unroll
        for (int e = 0; e < 2; e++) {
            float p1 = __expf(acc[nt][e] - gm1);
            float p2 = __expf(acc[nt][2 + e] - gm2);
            acc[nt][e] = p1;
            acc[nt][2 + e] = p2;
            su1 += p1;
            su2 += p2;
        }
    }
    su1 += __shfl_xor_sync(0xffffffffu, su1, 1);
    su1 += __shfl_xor_sync(0xffffffffu, su1, 2);
    su2 += __shfl_xor_sync(0xffffffffu, su2, 1);
    su2 += __shfl_xor_sync(0xffffffffu, su2, 2);
    if ((lane & 3) == 0) {
        ssum[h * 64 + r1] = su1;
        ssum[h * 64 + r2] = su2;
    }

    // Stage transposed V into the retired K region
    for (int idx = tid; idx < 192 * 16; idx += 256) {
        int j = idx >> 4, d4 = (idx & 15) << 2;
        int jg = t0 - 64 + j;
        float4 vv = make_float4(0.f, 0.f, 0.f, 0.f);
        if (jg >= 0 && jg < T_)
            vv = *(const float4*)(Vg + (size_t)jg * P_ + d4);
        float vals[4] = {vv.x, vv.y, vv.z, vv.w};
#pragma unroll
        for (int i = 0; i < 4; i++) {
            int d = d4 + i;
            __nv_bfloat16 vh = __float2bfloat16_rn(vals[i]);
            *(__nv_bfloat16*)(smem + AT_VH + d * 400 + j * 2) = vh;
            *(__nv_bfloat16*)(smem + AT_VL + d * 400 + j * 2) =
                __float2bfloat16_rn(vals[i] - __bfloat162float(vh));
        }
    }

    uint32_t ph[24], pl[24];
#pragma unroll
    for (int nt = 0; nt < 12; nt++) {
        __nv_bfloat162 h01 = __floats2bfloat162_rn(acc[nt][0], acc[nt][1]);
        __nv_bfloat162 h23 = __floats2bfloat162_rn(acc[nt][2], acc[nt][3]);
        ph[2 * nt]     = b2u(h01);
        ph[2 * nt + 1] = b2u(h23);
        pl[2 * nt]     = b2u(__floats2bfloat162_rn(acc[nt][0] - __low2float(h01),
                                                   acc[nt][1] - __high2float(h01)));
        pl[2 * nt + 1] = b2u(__floats2bfloat162_rn(acc[nt][2] - __low2float(h23),
                                                   acc[nt][3] - __high2float(h23)));
    }
    __syncthreads();

    const uint32_t vt_off = (uint32_t)(((lane & 7) + ((lane & 16) >> 1)) * 400
                                       + ((lane & 8) << 1) + h * 192);
    float oacc[8][4];
#pragma unroll
    for (int nt = 0; nt < 8; nt++)
#pragma unroll
        for (int c = 0; c < 4; c++) oacc[nt][c] = 0.f;

#pragma unroll
    for (int kk = 0; kk < 6; ++kk) {
        const uint32_t* aph = ph + kk * 4;
        const uint32_t* apl = pl + kk * 4;
#pragma unroll
        for (int nv = 0; nv < 4; ++nv) {
            uint32_t vb = sb + vt_off + (uint32_t)(nv * 6400) + kk * 32;
            uint32_t vh4[4], vl4[4];
            ldsm4(vh4, vb + AT_VH);
            ldsm4(vl4, vb + AT_VL);
#pragma unroll
            for (int hh = 0; hh < 2; ++hh) {
                const int nt = nv * 2 + hh;
                mma16816(oacc[nt], aph, vh4[2 * hh], vh4[2 * hh + 1]);
                mma16816(oacc[nt], aph, vl4[2 * hh], vl4[2 * hh + 1]);
                mma16816(oacc[nt], apl, vh4[2 * hh], vh4[2 * hh + 1]);
            }
        }
    }

    float* part = (float*)(smem + AT_PART);
    if (h == 1) {
#pragma unroll
        for (int nt = 0; nt < 8; nt++) {
            int col = nt * 8 + 2 * (lane & 3);
            *(float2*)(part + r1 * 66 + col) = make_float2(oacc[nt][0], oacc[nt][1]);
            *(float2*)(part + r2 * 66 + col) = make_float2(oacc[nt][2], oacc[nt][3]);
        }
    }
    __syncthreads();
    if (h == 0) {
        const float inv1 = 1.f / (ssum[r1] + ssum[64 + r1]);
        const float inv2 = 1.f / (ssum[r2] + ssum[64 + r2]);
        float* O1 = g_att + ((size_t)b * T_ + t0 + r1) * P_;
        float* O2 = g_att + ((size_t)b * T_ + t0 + r2) * P_;
#pragma unroll
        for (int nt = 0; nt < 8; nt++) {
            int col = nt * 8 + 2 * (lane & 3);
            float2 p1 = *(float2*)(part + r1 * 66 + col);
            float2 p2 = *(float2*)(part + r2 * 66 + col);
            *(float2*)(O1 + col) = make_float2((oacc[nt][0] + p1.x) * inv1,
                                               (oacc[nt][1] + p1.y) * inv1);
            *(float2*)(O2 + col) = make_float2((oacc[nt][2] + p2.x) * inv2,
                                               (oacc[nt][3] + p2.y) * inv2);
        }
    }
}

// ---------------------------------------------------------------------------
// Kernel 3: output projection, persistent m-block — de-hoisted A fragments
// so regs <= 128 -> 2 CTA/SM (1 wave).  A fragments reloaded per n-tile
// (+16 ldsm/tile, ~2% issue).  __launch_bounds__(256, 2) pins the target.
// ---------------------------------------------------------------------------
#define OP2_AH 0
#define OP2_AL 9216
#define OP2_B  18432
#define OP2_BSTAGE 36864
#define OP2_SMEM (18432 + 2 * 36864)   // 92160

__global__ __launch_bounds__(256, 2) void outproj_mma(
    const float* __restrict__ bo, float* __restrict__ O)
{
    extern __shared__ char smem[];
    const uint32_t sb = smem_u32(smem);
    const int tid = threadIdx.x, lane = tid & 31, wid = tid >> 5;
    const int wm = wid >> 2, wn = wid & 3;
    const int m0 = blockIdx.x * 64;

    {
        int row = tid >> 2, ks = (tid & 3) * 16;
        const float* ap = g_att + (size_t)(m0 + row) * P_ + ks;
        float4 f0 = *(const float4*)(ap + 0);
        float4 f1 = *(const float4*)(ap + 4);
        float4 f2 = *(const float4*)(ap + 8);
        float4 f3 = *(const float4*)(ap + 12);
        uint4 hi0, lo0, hi1, lo1;
        split8(f0, f1, hi0, lo0);
        split8(f2, f3, hi1, lo1);
        *(uint4*)(smem + OP2_AH + row * 144 + ks * 2)      = hi0;
        *(uint4*)(smem + OP2_AH + row * 144 + ks * 2 + 16) = hi1;
        *(uint4*)(smem + OP2_AL + row * 144 + ks * 2)      = lo0;
        *(uint4*)(smem + OP2_AL + row * 144 + ks * 2 + 16) = lo1;
    }

    uint4 brh[4], brl[4];
#define OP_LDG(nb) do {                                                          \
    int n0 = (nb) * 128;                                                         \
    _Pragma("unroll")                                                            \
    for (int i = 0; i < 4; i++) {                                                \
        int idx = tid + i * 256; int n = idx >> 3, sg = idx & 7;                 \
        brh[i] = *(const uint4*)(g_wo_hi + (size_t)(n0 + n) * P_ + sg * 8);      \
        brl[i] = *(const uint4*)(g_wo_lo + (size_t)(n0 + n) * P_ + sg * 8);      \
    } } while (0)

#define OP_STS(s) do {                                                           \
    char* bp = smem + OP2_B + (s) * OP2_BSTAGE;                                  \
    _Pragma("unroll")                                                            \
    for (int i = 0; i < 4; i++) {                                                \
        int idx = tid + i * 256; int n = idx >> 3, sg = idx & 7;                 \
        *(uint4*)(bp + n * 144 + sg * 16)         = brh[i];                      \
        *(uint4*)(bp + 18432 + n * 144 + sg * 16) = brl[i];                      \
    } } while (0)

    OP_LDG(0);
    __syncthreads();
    OP_STS(0);
    __syncthreads();

    const uint32_t a_off = (uint32_t)((wm * 32 + (lane & 15)) * 144 + (lane & 16));
    const uint32_t b_off = (uint32_t)((wn * 32 + (lane & 7) + ((lane & 16) >> 1)) * 144
                                      + ((lane & 8) << 1));
    const int r0 = m0 + wm * 32 + (lane >> 2);

    for (int nb = 0; nb < 8; ++nb) {
        const int s = nb & 1;
        if (nb < 7) OP_LDG(nb + 1);

        float acc[2][4][4];
#pragma unroll
        for (int i = 0; i < 2; i++)
#pragma unroll
            for (int j = 0; j < 4; j++)
#pragma unroll
                for (int c = 0; c < 4; c++) acc[i][j][c] = 0.f;

        const uint32_t bbase = sb + OP2_B + s * OP2_BSTAGE;
#pragma unroll
        for (int ks = 0; ks < 4; ++ks) {
            uint32_t ah[2][4], al[2][4];
#pragma unroll
            for (int mt = 0; mt < 2; ++mt) {
                ldsm4(ah[mt], sb + OP2_AH + a_off + mt * 2304 + ks * 32);
                ldsm4(al[mt], sb + OP2_AL + a_off + mt * 2304 + ks * 32);
            }
#pragma unroll
            for (int np = 0; np < 2; ++np) {
                uint32_t bh[4], bl[4];
                ldsm4(bh, bbase + b_off + np * 2304 + ks * 32);
                ldsm4(bl, bbase + 18432 + b_off + np * 2304 + ks * 32);
#pragma unroll
                for (int hh = 0; hh < 2; ++hh) {
                    const int nt = np * 2 + hh;
#pragma unroll
                    for (int mt = 0; mt < 2; ++mt) {
                        mma16816(acc[mt][nt], ah[mt], bh[2 * hh], bh[2 * hh + 1]);
                        mma16816(acc[mt][nt], ah[mt], bl[2 * hh], bl[2 * hh + 1]);
                        mma16816(acc[mt][nt], al[mt], bh[2 * hh], bh[2 * hh + 1]);
                    }
                }
            }
        }

        const int n0 = nb * 128;
#pragma unroll
        for (int mt = 0; mt < 2; ++mt)
#pragma unroll
            for (int nt = 0; nt < 4; ++nt) {
                int n = n0 + wn * 32 + nt * 8 + (lane & 3) * 2;
                int row = r0 + mt * 16;
                float b0 = __ldg(bo + n), b1 = __ldg(bo + n + 1);
                *(float2*)(O + (size_t)row * H_ + n) =
                    make_float2(acc[mt][nt][0] + b0, acc[mt][nt][1] + b1);
                *(float2*)(O + (size_t)(row + 8) * H_ + n) =
                    make_float2(acc[mt][nt][2] + b0, acc[mt][nt][3] + b1);
            }

        if (nb < 7) { OP_STS(s ^ 1); __syncthreads(); }
    }
}

// ---------------------------------------------------------------------------
// Launch
// ---------------------------------------------------------------------------
extern "C" void kernel_launch(void* const* d_in, const int* in_sizes, int n_in,
                              void* d_out, int out_size)
{
    (void)in_sizes; (void)n_in; (void)out_size;
    const float* X    = (const float*)d_in[0];
    const float* Wq   = (const float*)d_in[2];
    const float* bq   = (const float*)d_in[3];
    const float* Wk   = (const float*)d_in[4];
    const float* bk   = (const float*)d_in[5];
    const float* Wv   = (const float*)d_in[6];
    const float* bv   = (const float*)d_in[7];
    const float* Wo   = (const float*)d_in[8];
    const float* bo   = (const float*)d_in[9];
    const float* bias = (const float*)d_in[10];
    float* O = (float*)d_out;

    prep_all<<<448, 256>>>(Wq, Wk, Wv, Wo);

    cudaFuncSetAttribute(qkv_mma, cudaFuncAttributeMaxDynamicSharedMemorySize,
                         QKV_SMEM);
    qkv_mma<<<128, 256, QKV_SMEM>>>(X, bq, bk, bv);

    cudaFuncSetAttribute(attn_mma, cudaFuncAttributeMaxDynamicSharedMemorySize,
                         AT_SMEM);
    attn_mma<<<256, 256, AT_SMEM>>>(bias);

    cudaFuncSetAttribute(outproj_mma, cudaFuncAttributeMaxDynamicSharedMemorySize,
                         OP2_SMEM);
    outproj_mma<<<256, 256, OP2_SMEM>>>(bo, O);
}

// round 15
// speedup vs baseline: 2.7566x; 1.0047x over previous
#include <cuda_runtime.h>
#include <cuda_bf16.h>
#include <cstdint>

#define B_ 8
#define T_ 2048
#define H_ 1024
#define P_ 64
#define BT_ (B_ * T_)

// Scratch (no cudaMalloc allowed)
__device__ float g_q[BT_ * P_];
__device__ float g_k[BT_ * P_];
__device__ float g_v[BT_ * P_];
__device__ float g_att[BT_ * P_];
// QKV weights transposed to [n][k] (n=192, k=1024), split bf16 hi/lo
__device__ __align__(16) __nv_bfloat16 g_wt_hi[192 * 1024];
__device__ __align__(16) __nv_bfloat16 g_wt_lo[192 * 1024];
// Wo in mma B-fragment layout: [n8-tile(128)][k16-tile(4)][lane(32)] uint2
// uint2.x = bf16x2 (k=2t,2t+1), .y = (k=2t+8,2t+9) at n = tile*8 + lane/4
__device__ __align__(16) uint2 g_wo_fh[128 * 4 * 32];
__device__ __align__(16) uint2 g_wo_fl[128 * 4 * 32];

// ---------------------------------------------------------------------------
// Base-ISA tensor helpers (sm_80+; compile at plain sm_103)
// ---------------------------------------------------------------------------
__device__ __forceinline__ uint32_t smem_u32(const void* p) {
    uint32_t a;
    asm("{ .reg .u64 t; cvta.to.shared.u64 t, %1; cvt.u32.u64 %0, t; }"
        : "=r"(a) : "l"(p));
    return a;
}

__device__ __forceinline__ void ldsm4(uint32_t* r, uint32_t addr) {
    asm volatile("ldmatrix.sync.aligned.m8n8.x4.shared.b16 {%0,%1,%2,%3}, [%4];"
                 : "=r"(r[0]), "=r"(r[1]), "=r"(r[2]), "=r"(r[3]) : "r"(addr));
}

__device__ __forceinline__ void mma16816(float* d, const uint32_t* a,
                                         uint32_t b0, uint32_t b1) {
    asm volatile(
        "mma.sync.aligned.m16n8k16.row.col.f32.bf16.bf16.f32 "
        "{%0,%1,%2,%3}, {%4,%5,%6,%7}, {%8,%9}, {%0,%1,%2,%3};"
        : "+f"(d[0]), "+f"(d[1]), "+f"(d[2]), "+f"(d[3])
        : "r"(a[0]), "r"(a[1]), "r"(a[2]), "r"(a[3]), "r"(b0), "r"(b1));
}

__device__ __forceinline__ uint32_t b2u(__nv_bfloat162 v) {
    union { __nv_bfloat162 b; uint32_t u; } c;
    c.b = v;
    return c.u;
}

// Split 8 fp32 into bf16 hi (uint4) and residual lo (uint4)
__device__ __forceinline__ void split8(float4 a, float4 b, uint4& hi, uint4& lo) {
    __nv_bfloat162 h01 = __floats2bfloat162_rn(a.x, a.y);
    __nv_bfloat162 h23 = __floats2bfloat162_rn(a.z, a.w);
    __nv_bfloat162 h45 = __floats2bfloat162_rn(b.x, b.y);
    __nv_bfloat162 h67 = __floats2bfloat162_rn(b.z, b.w);
    __nv_bfloat162 l01 = __floats2bfloat162_rn(a.x - __low2float(h01), a.y - __high2float(h01));
    __nv_bfloat162 l23 = __floats2bfloat162_rn(a.z - __low2float(h23), a.w - __high2float(h23));
    __nv_bfloat162 l45 = __floats2bfloat162_rn(b.x - __low2float(h45), b.y - __high2float(h45));
    __nv_bfloat162 l67 = __floats2bfloat162_rn(b.z - __low2float(h67), b.w - __high2float(h67));
    hi = make_uint4(b2u(h01), b2u(h23), b2u(h45), b2u(h67));
    lo = make_uint4(b2u(l01), b2u(l23), b2u(l45), b2u(l67));
}

// Split 4 fp32 into bf16 hi (uint2) and residual lo (uint2)
__device__ __forceinline__ void split4(float4 v, uint2& hi, uint2& lo) {
    __nv_bfloat162 h01 = __floats2bfloat162_rn(v.x, v.y);
    __nv_bfloat162 h23 = __floats2bfloat162_rn(v.z, v.w);
    __nv_bfloat162 l01 = __floats2bfloat162_rn(v.x - __low2float(h01), v.y - __high2float(h01));
    __nv_bfloat162 l23 = __floats2bfloat162_rn(v.z - __low2float(h23), v.w - __high2float(h23));
    hi = make_uint2(b2u(h01), b2u(h23));
    lo = make_uint2(b2u(l01), b2u(l23));
}

// ---------------------------------------------------------------------------
// Prep: blocks 0-191 transpose+split QKV weights; blocks 192-255 build the
// Wo B-fragment arrays (16384 lanes, one fragment pair per thread).
// ---------------------------------------------------------------------------
__global__ void prep_all(const float* __restrict__ Wq, const float* __restrict__ Wk,
                         const float* __restrict__ Wv, const float* __restrict__ Wo) {
    int bid = blockIdx.x;
    if (bid < 192) {
        int n = bid;
        const float* W = (n < 64) ? Wq : ((n < 128) ? Wk : Wv);
        int col = n & 63;
        for (int k = threadIdx.x; k < H_; k += 256) {
            float w = W[(size_t)k * P_ + col];
            __nv_bfloat16 h = __float2bfloat16_rn(w);
            g_wt_hi[(size_t)n * H_ + k] = h;
            g_wt_lo[(size_t)n * H_ + k] = __float2bfloat16_rn(w - __bfloat162float(h));
        }
    } else {
        int idx = (bid - 192) * 256 + threadIdx.x;   // 0..16383
        int lane = idx & 31;
        int ks   = (idx >> 5) & 3;
        int g8   = idx >> 7;                          // n8-tile 0..127
        int n = g8 * 8 + (lane >> 2);                 // 0..1023
        int k = ks * 16 + (lane & 3) * 2;             // 0..62
        float w0 = Wo[(size_t)(k + 0) * H_ + n];
        float w1 = Wo[(size_t)(k + 1) * H_ + n];
        float w8 = Wo[(size_t)(k + 8) * H_ + n];
        float w9 = Wo[(size_t)(k + 9) * H_ + n];
        __nv_bfloat162 h01 = __floats2bfloat162_rn(w0, w1);
        __nv_bfloat162 h89 = __floats2bfloat162_rn(w8, w9);
        __nv_bfloat162 l01 = __floats2bfloat162_rn(w0 - __low2float(h01),
                                                   w1 - __high2float(h01));
        __nv_bfloat162 l89 = __floats2bfloat162_rn(w8 - __low2float(h89),
                                                   w9 - __high2float(h89));
        g_wo_fh[idx] = make_uint2(b2u(h01), b2u(h89));
        g_wo_fl[idx] = make_uint2(b2u(l01), b2u(l89));
    }
}

// ---------------------------------------------------------------------------
// Kernel 1: fused QKV projection via mma.sync (unchanged from R11)
// ---------------------------------------------------------------------------
#define QKV_STAGE 51200
#define QKV_AH 0
#define QKV_AL 10240
#define QKV_BH 20480
#define QKV_BL 35840
#define QKV_SMEM (1024 + 2 * QKV_STAGE)   // 103424

__global__ __launch_bounds__(256) void qkv_mma(
    const float* __restrict__ X,
    const float* __restrict__ bq, const float* __restrict__ bk,
    const float* __restrict__ bv)
{
    extern __shared__ char smem[];
    const uint32_t sb = smem_u32(smem);
    const int tid = threadIdx.x, lane = tid & 31, wid = tid >> 5;
    const int wm = wid >> 2, wn = wid & 3;
    const int m0 = blockIdx.x * 128;

    float* bias_s = (float*)smem;
    if (tid < 192)
        bias_s[tid] = (tid < 64) ? bq[tid] : ((tid < 128) ? bk[tid - 64] : bv[tid - 128]);

    const int a_row = tid >> 1;
    const int a_seg = (tid & 1) * 16;
    const float* Xrow = X + (size_t)(m0 + a_row) * H_ + a_seg;

    const uint32_t a_off = (uint32_t)((wm * 64 + (lane & 15)) * 80 + (lane & 16));
    const uint32_t b_off = (uint32_t)((wn * 48 + (lane & 7) + ((lane & 16) >> 1)) * 80
                                      + ((lane & 8) << 1));

    float4 ar0, ar1, ar2, ar3;
    uint4 brh[3], brl[3];

    float acc[4][6][4];
#pragma unroll
    for (int i = 0; i < 4; i++)
#pragma unroll
        for (int j = 0; j < 6; j++)
#pragma unroll
            for (int c = 0; c < 4; c++) acc[i][j][c] = 0.f;

#define QKV_LDG(c) do {                                                          \
    int k0 = (c) * 32;                                                           \
    ar0 = *(const float4*)(Xrow + k0);                                           \
    ar1 = *(const float4*)(Xrow + k0 + 4);                                       \
    ar2 = *(const float4*)(Xrow + k0 + 8);                                       \
    ar3 = *(const float4*)(Xrow + k0 + 12);                                      \
    _Pragma("unroll")                                                            \
    for (int i = 0; i < 3; i++) {                                                \
        int idx = tid + i * 256; int n = idx >> 2, sg = idx & 3;                 \
        brh[i] = *(const uint4*)(g_wt_hi + (size_t)n * H_ + k0 + sg * 8);        \
        brl[i] = *(const uint4*)(g_wt_lo + (size_t)n * H_ + k0 + sg * 8);        \
    } } while (0)

#define QKV_STS(s) do {                                                          \
    char* bp = smem + 1024 + (s) * QKV_STAGE;                                    \
    uint4 hi0, lo0, hi1, lo1;                                                    \
    split8(ar0, ar1, hi0, lo0);                                                  \
    split8(ar2, ar3, hi1, lo1);                                                  \
    *(uint4*)(bp + QKV_AH + a_row * 80 + a_seg * 2)      = hi0;                  \
    *(uint4*)(bp + QKV_AH + a_row * 80 + a_seg * 2 + 16) = hi1;                  \
    *(uint4*)(bp + QKV_AL + a_row * 80 + a_seg * 2)      = lo0;                  \
    *(uint4*)(bp + QKV_AL + a_row * 80 + a_seg * 2 + 16) = lo1;                  \
    _Pragma("unroll")                                                            \
    for (int i = 0; i < 3; i++) {                                                \
        int idx = tid + i * 256; int n = idx >> 2, sg = idx & 3;                 \
        *(uint4*)(bp + QKV_BH + n * 80 + sg * 16) = brh[i];                      \
        *(uint4*)(bp + QKV_BL + n * 80 + sg * 16) = brl[i];                      \
    } } while (0)

    QKV_LDG(0);
    QKV_STS(0);
    __syncthreads();

    for (int c = 0; c < 32; ++c) {
        const int s = c & 1;
        if (c < 31) QKV_LDG(c + 1);
        const uint32_t base = sb + 1024 + s * QKV_STAGE;
#pragma unroll
        for (int ks = 0; ks < 2; ++ks) {
            uint32_t ah[4][4], al[4][4];
#pragma unroll
            for (int mt = 0; mt < 4; mt++) {
                ldsm4(ah[mt], base + QKV_AH + a_off + mt * 1280 + ks * 32);
                ldsm4(al[mt], base + QKV_AL + a_off + mt * 1280 + ks * 32);
            }
#pragma unroll
            for (int np = 0; np < 3; ++np) {
                uint32_t bh[4], bl[4];
                ldsm4(bh, base + QKV_BH + b_off + np * 1280 + ks * 32);
                ldsm4(bl, base + QKV_BL + b_off + np * 1280 + ks * 32);
#pragma unroll
                for (int hh = 0; hh < 2; ++hh) {
                    const int nt = np * 2 + hh;
#pragma unroll
                    for (int mt = 0; mt < 4; mt++) {
                        mma16816(acc[mt][nt], ah[mt], bh[2 * hh], bh[2 * hh + 1]);
                        mma16816(acc[mt][nt], ah[mt], bl[2 * hh], bl[2 * hh + 1]);
                        mma16816(acc[mt][nt], al[mt], bh[2 * hh], bh[2 * hh + 1]);
                    }
                }
            }
        }
        if (c < 31) { QKV_STS(s ^ 1); __syncthreads(); }
    }

    const int r0 = m0 + wm * 64 + (lane >> 2);
#pragma unroll
    for (int mt = 0; mt < 4; ++mt)
#pragma unroll
        for (int nt = 0; nt < 6; ++nt) {
            int n = wn * 48 + nt * 8 + (lane & 3) * 2;
            float* out = (n < 64) ? g_q : ((n < 128) ? g_k : g_v);
            int cn = n & 63;
            int row = r0 + mt * 16;
            float b0 = bias_s[n], b1 = bias_s[n + 1];
            *(float2*)(out + (size_t)row * P_ + cn) =
                make_float2(acc[mt][nt][0] + b0, acc[mt][nt][1] + b1);
            *(float2*)(out + (size_t)(row + 8) * P_ + cn) =
                make_float2(acc[mt][nt][2] + b0, acc[mt][nt][3] + b1);
        }
}

// ---------------------------------------------------------------------------
// Kernel 2: banded attention via mma.sync — smem lifetime overlap (R13, 2 CTA/SM)
// ---------------------------------------------------------------------------
#define AT_KH   0
#define AT_KL   27648
#define AT_VH   0
#define AT_VL   25600
#define AT_QH   55296
#define AT_QL   64512
#define AT_PART 55296
#define AT_BIAS 73728
#define AT_MAX  74496
#define AT_SUM  75008
#define AT_SMEM 75520

__global__ __launch_bounds__(256, 2) void attn_mma(const float* __restrict__ biasg)
{
    extern __shared__ char smem[];
    const uint32_t sb = smem_u32(smem);
    const int tid = threadIdx.x, lane = tid & 31, w = tid >> 5;
    const int h = w >> 2, rb = w & 3;
    const int b  = blockIdx.x >> 5;
    const int t0 = (blockIdx.x & 31) << 6;

    const float* Kg = g_k + (size_t)b * T_ * P_;
    const float* Vg = g_v + (size_t)b * T_ * P_;
    const float* Qg = g_q + ((size_t)b * T_ + t0) * P_;

    for (int idx = tid; idx < 192 * 16; idx += 256) {
        int j = idx >> 4, d4 = (idx & 15) << 2;
        int jg = t0 - 64 + j;
        float4 kv = make_float4(0.f, 0.f, 0.f, 0.f);
        if (jg >= 0 && jg < T_)
            kv = *(const float4*)(Kg + (size_t)jg * P_ + d4);
        uint2 khi, klo;
        split4(kv, khi, klo);
        *(uint2*)(smem + AT_KH + j * 144 + d4 * 2) = khi;
        *(uint2*)(smem + AT_KL + j * 144 + d4 * 2) = klo;
    }
    for (int idx = tid; idx < 64 * 16; idx += 256) {
        int r = idx >> 4, d4 = (idx & 15) << 2;
        float4 qv = *(const float4*)(Qg + (size_t)r * P_ + d4);
        uint2 qhi, qlo;
        split4(qv, qhi, qlo);
        *(uint2*)(smem + AT_QH + r * 144 + d4 * 2) = qhi;
        *(uint2*)(smem + AT_QL + r * 144 + d4 * 2) = qlo;
    }
    float* bias_s = (float*)(smem + AT_BIAS);
    for (int d = tid; d < 192; d += 256)
        bias_s[d] = (d <= 128) ? biasg[1984 + d] : 0.f;
    __syncthreads();

    const uint32_t a_off = (uint32_t)((rb * 16 + (lane & 15)) * 144 + (lane & 16));
    const uint32_t b_off = (uint32_t)(((lane & 7) + ((lane & 16) >> 1)) * 144
                                      + ((lane & 8) << 1));
    float acc[12][4];
#pragma unroll
    for (int nt = 0; nt < 12; nt++)
#pragma unroll
        for (int c = 0; c < 4; c++) acc[nt][c] = 0.f;

#pragma unroll
    for (int ks = 0; ks < 4; ++ks) {
        uint32_t qh[4], ql[4];
        ldsm4(qh, sb + AT_QH + a_off + ks * 32);
        ldsm4(ql, sb + AT_QL + a_off + ks * 32);
#pragma unroll
        for (int np = 0; np < 6; ++np) {
            uint32_t kb = sb + b_off + (uint32_t)((h * 96 + np * 16) * 144) + ks * 32;
            uint32_t kh4[4], kl4[4];
            ldsm4(kh4, kb + AT_KH);
            ldsm4(kl4, kb + AT_KL);
#pragma unroll
            for (int hh = 0; hh < 2; ++hh) {
                const int nt = np * 2 + hh;
                mma16816(acc[nt], qh, kh4[2 * hh], kh4[2 * hh + 1]);
                mma16816(acc[nt], qh, kl4[2 * hh], kl4[2 * hh + 1]);
                mma16816(acc[nt], ql, kh4[2 * hh], kh4[2 * hh + 1]);
            }
        }
    }

    const int r1 = rb * 16 + (lane >> 2);
    const int r2 = r1 + 8;
    float* smax = (float*)(smem + AT_MAX);
    float* ssum = (float*)(smem + AT_SUM);

    float m1 = -1e30f, m2v = -1e30f;
#pragma unroll
    for (int nt = 0; nt < 12; nt++) {
        int cbase = h * 96 + nt * 8 + 2 * (lane & 3);
#pragma unroll
        for (int e = 0; e < 2; e++) {
            int c = cbase + e;
            int jg = t0 - 64 + c;
            bool jv = (jg >= 0 && jg < T_);
            int rel1 = c - r1;
            bool v1 = jv && rel1 >= 0 && rel1 <= 128;
            float s1v = v1 ? fmaf(acc[nt][e], 0.125f, bias_s[rel1]) : -1e30f;
            acc[nt][e] = s1v;
            m1 = fmaxf(m1, s1v);
            int rel2 = c - r2;
            bool v2 = jv && rel2 >= 0 && rel2 <= 128;
            float s2v = v2 ? fmaf(acc[nt][2 + e], 0.125f, bias_s[rel2]) : -1e30f;
            acc[nt][2 + e] = s2v;
            m2v = fmaxf(m2v, s2v);
        }
    }
    m1  = fmaxf(m1,  __shfl_xor_sync(0xffffffffu, m1, 1));
    m1  = fmaxf(m1,  __shfl_xor_sync(0xffffffffu, m1, 2));
    m2v = fmaxf(m2v, __shfl_xor_sync(0xffffffffu, m2v, 1));
    m2v = fmaxf(m2v, __shfl_xor_sync(0xffffffffu, m2v, 2));
    if ((lane & 3) == 0) {
        smax[h * 64 + r1] = m1;
        smax[h * 64 + r2] = m2v;
    }
    __syncthreads();
    const float gm1 = fmaxf(smax[r1], smax[64 + r1]);
    const float gm2 = fmaxf(smax[r2], smax[64 + r2]);

    float su1 = 0.f, su2 = 0.f;
#pragma unroll
    for (int nt = 0; nt < 12; nt++) {
#pragma unroll
        for (int e = 0; e < 2; e++) {
            float p1 = __expf(acc[nt][e] - gm1);
            float p2 = __expf(acc[nt][2 + e] - gm2);
            acc[nt][e] = p1;
            acc[nt][2 + e] = p2;
            su1 += p1;
            su2 += p2;
        }
    }
    su1 += __shfl_xor_sync(0xffffffffu, su1, 1);
    su1 += __shfl_xor_sync(0xffffffffu, su1, 2);
    su2 += __shfl_xor_sync(0xffffffffu, su2, 1);
    su2 += __shfl_xor_sync(0xffffffffu, su2, 2);
    if ((lane & 3) == 0) {
        ssum[h * 64 + r1] = su1;
        ssum[h * 64 + r2] = su2;
    }

    // Stage transposed V into the retired K region
    for (int idx = tid; idx < 192 * 16; idx += 256) {
        int j = idx >> 4, d4 = (idx & 15) << 2;
        int jg = t0 - 64 + j;
        float4 vv = make_float4(0.f, 0.f, 0.f, 0.f);
        if (jg >= 0 && jg < T_)
            vv = *(const float4*)(Vg + (size_t)jg * P_ + d4);
        float vals[4] = {vv.x, vv.y, vv.z, vv.w};
#pragma unroll
        for (int i = 0; i < 4; i++) {
            int d = d4 + i;
            __nv_bfloat16 vh = __float2bfloat16_rn(vals[i]);
            *(__nv_bfloat16*)(smem + AT_VH + d * 400 + j * 2) = vh;
            *(__nv_bfloat16*)(smem + AT_VL + d * 400 + j * 2) =
                __float2bfloat16_rn(vals[i] - __bfloat162float(vh));
        }
    }

    uint32_t ph[24], pl[24];
#pragma unroll
    for (int nt = 0; nt < 12; nt++) {
        __nv_bfloat162 h01 = __floats2bfloat162_rn(acc[nt][0], acc[nt][1]);
        __nv_bfloat162 h23 = __floats2bfloat162_rn(acc[nt][2], acc[nt][3]);
        ph[2 * nt]     = b2u(h01);
        ph[2 * nt + 1] = b2u(h23);
        pl[2 * nt]     = b2u(__floats2bfloat162_rn(acc[nt][0] - __low2float(h01),
                                                   acc[nt][1] - __high2float(h01)));
        pl[2 * nt + 1] = b2u(__floats2bfloat162_rn(acc[nt][2] - __low2float(h23),
                                                   acc[nt][3] - __high2float(h23)));
    }
    __syncthreads();

    const uint32_t vt_off = (uint32_t)(((lane & 7) + ((lane & 16) >> 1)) * 400
                                       + ((lane & 8) << 1) + h * 192);
    float oacc[8][4];
#pragma unroll
    for (int nt = 0; nt < 8; nt++)
#pragma unroll
        for (int c = 0; c < 4; c++) oacc[nt][c] = 0.f;

#pragma unroll
    for (int kk = 0; kk < 6; ++kk) {
        const uint32_t* aph = ph + kk * 4;
        const uint32_t* apl = pl + kk * 4;
#pragma unroll
        for (int nv = 0; nv < 4; ++nv) {
            uint32_t vb = sb + vt_off + (uint32_t)(nv * 6400) + kk * 32;
            uint32_t vh4[4], vl4[4];
            ldsm4(vh4, vb + AT_VH);
            ldsm4(vl4, vb + AT_VL);
#pragma unroll
            for (int hh = 0; hh < 2; ++hh) {
                const int nt = nv * 2 + hh;
                mma16816(oacc[nt], aph, vh4[2 * hh], vh4[2 * hh + 1]);
                mma16816(oacc[nt], aph, vl4[2 * hh], vl4[2 * hh + 1]);
                mma16816(oacc[nt], apl, vh4[2 * hh], vh4[2 * hh + 1]);
            }
        }
    }

    float* part = (float*)(smem + AT_PART);
    if (h == 1) {
#pragma unroll
        for (int nt = 0; nt < 8; nt++) {
            int col = nt * 8 + 2 * (lane & 3);
            *(float2*)(part + r1 * 66 + col) = make_float2(oacc[nt][0], oacc[nt][1]);
            *(float2*)(part + r2 * 66 + col) = make_float2(oacc[nt][2], oacc[nt][3]);
        }
    }
    __syncthreads();
    if (h == 0) {
        const float inv1 = 1.f / (ssum[r1] + ssum[64 + r1]);
        const float inv2 = 1.f / (ssum[r2] + ssum[64 + r2]);
        float* O1 = g_att + ((size_t)b * T_ + t0 + r1) * P_;
        float* O2 = g_att + ((size_t)b * T_ + t0 + r2) * P_;
#pragma unroll
        for (int nt = 0; nt < 8; nt++) {
            int col = nt * 8 + 2 * (lane & 3);
            float2 p1 = *(float2*)(part + r1 * 66 + col);
            float2 p2 = *(float2*)(part + r2 * 66 + col);
            *(float2*)(O1 + col) = make_float2((oacc[nt][0] + p1.x) * inv1,
                                               (oacc[nt][1] + p1.y) * inv1);
            *(float2*)(O2 + col) = make_float2((oacc[nt][2] + p2.x) * inv2,
                                               (oacc[nt][3] + p2.y) * inv2);
        }
    }
}

// ---------------------------------------------------------------------------
// Kernel 3: output projection — B fragments loaded DIRECTLY from gmem
// (pre-laid-out by prep); no STS/ldsm/double-buffer for B.  BM=64, grid 256,
// warps 4m x 2n (warp tile 16m x 32n), A fragments hoisted (32 regs).
// smem: A hi/lo only (18.4 KB) -> 2 CTA/SM trivially.
// ---------------------------------------------------------------------------
#define OP3_AH 0
#define OP3_AL 9216
#define OP3_SMEM 18432

__global__ __launch_bounds__(256, 2) void outproj_mma(
    const float* __restrict__ bo, float* __restrict__ O)
{
    extern __shared__ char smem[];
    const uint32_t sb = smem_u32(smem);
    const int tid = threadIdx.x, lane = tid & 31, wid = tid >> 5;
    const int wm = wid >> 1, wn = wid & 1;
    const int m0 = blockIdx.x * 64;

    // Stage A (g_att 64x64 fp32 -> bf16 hi/lo, stride 144B)
    {
        int row = tid >> 2, ks = (tid & 3) * 16;
        const float* ap = g_att + (size_t)(m0 + row) * P_ + ks;
        float4 f0 = *(const float4*)(ap + 0);
        float4 f1 = *(const float4*)(ap + 4);
        float4 f2 = *(const float4*)(ap + 8);
        float4 f3 = *(const float4*)(ap + 12);
        uint4 hi0, lo0, hi1, lo1;
        split8(f0, f1, hi0, lo0);
        split8(f2, f3, hi1, lo1);
        *(uint4*)(smem + OP3_AH + row * 144 + ks * 2)      = hi0;
        *(uint4*)(smem + OP3_AH + row * 144 + ks * 2 + 16) = hi1;
        *(uint4*)(smem + OP3_AL + row * 144 + ks * 2)      = lo0;
        *(uint4*)(smem + OP3_AL + row * 144 + ks * 2 + 16) = lo1;
    }
    __syncthreads();

    // Hoist A fragments: warp covers rows wm*16..wm*16+15, all 4 k16 tiles
    const uint32_t a_off = (uint32_t)((wm * 16 + (lane & 15)) * 144 + (lane & 16));
    uint32_t ahf[4][4], alf[4][4];
#pragma unroll
    for (int ks = 0; ks < 4; ++ks) {
        ldsm4(ahf[ks], sb + OP3_AH + a_off + ks * 32);
        ldsm4(alf[ks], sb + OP3_AL + a_off + ks * 32);
    }

    const int r0 = m0 + wm * 16 + (lane >> 2);

    // Loop over 16 n-tiles of 64; warp handles n8-tiles g8 = nb*8 + wn*4 + j
    for (int nb = 0; nb < 16; ++nb) {
        float acc[4][4];
#pragma unroll
        for (int j = 0; j < 4; j++)
#pragma unroll
            for (int c = 0; c < 4; c++) acc[j][c] = 0.f;

        const int g8base = nb * 8 + wn * 4;
#pragma unroll
        for (int ks = 0; ks < 4; ++ks) {
#pragma unroll
            for (int j = 0; j < 4; ++j) {
                const int fi = ((g8base + j) * 4 + ks) * 32 + lane;
                uint2 bh = __ldg(&g_wo_fh[fi]);
                uint2 bl = __ldg(&g_wo_fl[fi]);
                mma16816(acc[j], ahf[ks], bh.x, bh.y);
                mma16816(acc[j], ahf[ks], bl.x, bl.y);
                mma16816(acc[j], alf[ks], bh.x, bh.y);
            }
        }

#pragma unroll
        for (int j = 0; j < 4; ++j) {
            int n = (g8base + j) * 8 + (lane & 3) * 2;
            float b0 = __ldg(bo + n), b1 = __ldg(bo + n + 1);
            *(float2*)(O + (size_t)r0 * H_ + n) =
                make_float2(acc[j][0] + b0, acc[j][1] + b1);
            *(float2*)(O + (size_t)(r0 + 8) * H_ + n) =
                make_float2(acc[j][2] + b0, acc[j][3] + b1);
        }
    }
}

// ---------------------------------------------------------------------------
// Launch
// ---------------------------------------------------------------------------
extern "C" void kernel_launch(void* const* d_in, const int* in_sizes, int n_in,
                              void* d_out, int out_size)
{
    (void)in_sizes; (void)n_in; (void)out_size;
    const float* X    = (const float*)d_in[0];
    const float* Wq   = (const float*)d_in[2];
    const float* bq   = (const float*)d_in[3];
    const float* Wk   = (const float*)d_in[4];
    const float* bk   = (const float*)d_in[5];
    const float* Wv   = (const float*)d_in[6];
    const float* bv   = (const float*)d_in[7];
    const float* Wo   = (const float*)d_in[8];
    const float* bo   = (const float*)d_in[9];
    const float* bias = (const float*)d_in[10];
    float* O = (float*)d_out;

    prep_all<<<256, 256>>>(Wq, Wk, Wv, Wo);

    cudaFuncSetAttribute(qkv_mma, cudaFuncAttributeMaxDynamicSharedMemorySize,
                         QKV_SMEM);
    qkv_mma<<<128, 256, QKV_SMEM>>>(X, bq, bk, bv);

    cudaFuncSetAttribute(attn_mma, cudaFuncAttributeMaxDynamicSharedMemorySize,
                         AT_SMEM);
    attn_mma<<<256, 256, AT_SMEM>>>(bias);

    cudaFuncSetAttribute(outproj_mma, cudaFuncAttributeMaxDynamicSharedMemorySize,
                         OP3_SMEM);
    outproj_mma<<<256, 256, OP3_SMEM>>>(bo, O);
}